// round 4
// baseline (speedup 1.0000x reference)
#include <cuda_runtime.h>
#include <math.h>
#include <stdint.h>

// Problem constants (fixed by setup_inputs)
#define Bb 2
#define Tt 2048
#define Dd 2048
#define NQ 16
#define NK 8
#define HD 128

// Scratch (device globals: allocation-free rule)
__device__ float g_q[(size_t)Bb * Tt * NQ * HD]; // 32 MB
__device__ float g_k[(size_t)Bb * Tt * NK * HD]; // 16 MB
__device__ float g_v[(size_t)Bb * Tt * NK * HD]; // 16 MB
__device__ float g_o[(size_t)Bb * Tt * NQ * HD]; // 32 MB
__device__ float g_sin[Tt * 64];
__device__ float g_cos[Tt * 64];

__device__ __forceinline__ float to_tf32(float x) {
    uint32_t r;
    asm("cvt.rna.tf32.f32 %0, %1;" : "=r"(r) : "f"(x));
    return __uint_as_float(r);
}

__device__ __forceinline__ void mma_tf32(float& d0, float& d1, float& d2, float& d3,
                                         uint32_t a0, uint32_t a1, uint32_t a2, uint32_t a3,
                                         uint32_t b0, uint32_t b1) {
    asm volatile(
        "mma.sync.aligned.m16n8k8.row.col.f32.tf32.tf32.f32 "
        "{%0,%1,%2,%3}, {%4,%5,%6,%7}, {%8,%9}, {%0,%1,%2,%3};"
        : "+f"(d0), "+f"(d1), "+f"(d2), "+f"(d3)
        : "r"(a0), "r"(a1), "r"(a2), "r"(a3), "r"(b0), "r"(b1));
}

// B-fragment smem offset for a 16-wide k-tile laid out as
// nb-blocks (8 cols) x 2 k-octets, 64 floats per block.
// element (kk in 0..15, n in 0..127):
//   block = (n>>3)*2 + (kk>>3); lane = ((n&7)<<2)+(kk&3); slot = (kk>>2)&1
__device__ __forceinline__ int bfrag_off(int kk, int n) {
    int block = ((n >> 3) << 1) + (kk >> 3);
    int lane2 = ((((n & 7) << 2) + (kk & 3)) << 1);
    int slot = (kk >> 2) & 1;
    return (block << 6) + lane2 + slot;
}

// ---------------------------------------------------------------------------
// tf32 GEMM with fragment-major smem staging + double buffering.
// C[M,N] = A[M,K] @ B[K,N], row-major fp32. Block 128x128x16, 256 thr, 8 warps
// (2x4 grid, warp tile 64x32).
// ---------------------------------------------------------------------------
__global__ __launch_bounds__(256) void gemm_tf32(const float* __restrict__ A,
                                                 const float* __restrict__ B,
                                                 float* __restrict__ C,
                                                 int M, int N, int K) {
    __shared__ float sAf[2][2048];
    __shared__ float sBf[2][2048];
    const int tid = threadIdx.x;
    const int bm = blockIdx.y << 7;
    const int bn = blockIdx.x << 7;
    const int warp = tid >> 5, lane = tid & 31;
    const int wm = (warp >> 2) << 6;
    const int wn = (warp & 3) << 5;
    const int grp = lane >> 2, qd = lane & 3;

    int ar[2], ac[2], br[2], bc[2];
#pragma unroll
    for (int u = 0; u < 2; u++) {
        int f = tid + (u << 8);
        ar[u] = f >> 2;          // 0..127
        ac[u] = (f & 3) << 2;    // 0,4,8,12
        br[u] = f >> 5;          // 0..15
        bc[u] = (f & 31) << 2;   // 0..124
    }

    float acc[4][4][4];
#pragma unroll
    for (int i = 0; i < 4; i++)
#pragma unroll
        for (int j = 0; j < 4; j++)
#pragma unroll
            for (int r = 0; r < 4; r++) acc[i][j][r] = 0.f;

    float4 pra[2], prb[2];
#pragma unroll
    for (int u = 0; u < 2; u++) {
        pra[u] = *(const float4*)(A + (size_t)(bm + ar[u]) * K + ac[u]);
        prb[u] = *(const float4*)(B + (size_t)br[u] * N + bn + bc[u]);
    }

    const int nkt = K >> 4;
#pragma unroll
    for (int u = 0; u < 2; u++) {
        int r = ar[u], c = ac[u];
        float* pa = &sAf[0][((((r >> 4) << 1) + (c >> 3)) << 7) + ((r & 7) << 4) +
                            (((c >> 2) & 1) << 1) + ((r >> 3) & 1)];
        pa[0] = to_tf32(pra[u].x); pa[4] = to_tf32(pra[u].y);
        pa[8] = to_tf32(pra[u].z); pa[12] = to_tf32(pra[u].w);
        float* pb = &sBf[0][bfrag_off(br[u], bc[u])];
        pb[0] = to_tf32(prb[u].x); pb[8] = to_tf32(prb[u].y);
        pb[16] = to_tf32(prb[u].z); pb[24] = to_tf32(prb[u].w);
    }
    __syncthreads();

    for (int kt = 0; kt < nkt; kt++) {
        const int buf = kt & 1;
        if (kt + 1 < nkt) {
            const int k0 = (kt + 1) << 4;
#pragma unroll
            for (int u = 0; u < 2; u++) {
                pra[u] = *(const float4*)(A + (size_t)(bm + ar[u]) * K + k0 + ac[u]);
                prb[u] = *(const float4*)(B + (size_t)(k0 + br[u]) * N + bn + bc[u]);
            }
        }
#pragma unroll
        for (int ko = 0; ko < 2; ko++) {
            uint4 af[4];
            uint2 bfr[4];
#pragma unroll
            for (int mt = 0; mt < 4; mt++)
                af[mt] = *(const uint4*)&sAf[buf][(((((wm >> 4) + mt) << 1) + ko) << 7) + (lane << 2)];
#pragma unroll
            for (int nt = 0; nt < 4; nt++)
                bfr[nt] = *(const uint2*)&sBf[buf][(((((wn >> 3) + nt) << 1) + ko) << 6) + (lane << 1)];
#pragma unroll
            for (int mt = 0; mt < 4; mt++)
#pragma unroll
                for (int nt = 0; nt < 4; nt++)
                    mma_tf32(acc[mt][nt][0], acc[mt][nt][1], acc[mt][nt][2], acc[mt][nt][3],
                             af[mt].x, af[mt].y, af[mt].z, af[mt].w,
                             bfr[nt].x, bfr[nt].y);
        }
        if (kt + 1 < nkt) {
            const int nb = buf ^ 1;
#pragma unroll
            for (int u = 0; u < 2; u++) {
                int r = ar[u], c = ac[u];
                float* pa = &sAf[nb][((((r >> 4) << 1) + (c >> 3)) << 7) + ((r & 7) << 4) +
                                     (((c >> 2) & 1) << 1) + ((r >> 3) & 1)];
                pa[0] = to_tf32(pra[u].x); pa[4] = to_tf32(pra[u].y);
                pa[8] = to_tf32(pra[u].z); pa[12] = to_tf32(pra[u].w);
                float* pb = &sBf[nb][bfrag_off(br[u], bc[u])];
                pb[0] = to_tf32(prb[u].x); pb[8] = to_tf32(prb[u].y);
                pb[16] = to_tf32(prb[u].z); pb[24] = to_tf32(prb[u].w);
            }
        }
        __syncthreads();
    }

#pragma unroll
    for (int mt = 0; mt < 4; mt++) {
#pragma unroll
        for (int nt = 0; nt < 4; nt++) {
            int row = bm + wm + (mt << 4) + grp;
            int col = bn + wn + (nt << 3) + (qd << 1);
            *(float2*)(C + (size_t)row * N + col) =
                make_float2(acc[mt][nt][0], acc[mt][nt][1]);
            *(float2*)(C + (size_t)(row + 8) * N + col) =
                make_float2(acc[mt][nt][2], acc[mt][nt][3]);
        }
    }
}

// ---------------------------------------------------------------------------
// RoPE table
// ---------------------------------------------------------------------------
__global__ __launch_bounds__(256) void rope_table() {
    int idx = blockIdx.x * 256 + threadIdx.x;
    if (idx >= Tt * 64) return;
    int t = idx >> 6, i = idx & 63;
    double ang = (double)t * exp(-0.21586735246819178 * (double)i);
    double s, c;
    sincos(ang, &s, &c);
    g_sin[idx] = (float)s;
    g_cos[idx] = (float)c;
}

// ---------------------------------------------------------------------------
// Fused RMSNorm + RoPE (table-based)
// ---------------------------------------------------------------------------
__global__ __launch_bounds__(128) void rms_rope(float* __restrict__ buf,
                                                const float* __restrict__ w,
                                                int heads) {
    const int idx = blockIdx.x;
    const int t = (idx / heads) % Tt;
    float* p = buf + (size_t)idx * HD;
    const int h = threadIdx.x;

    float x = p[h];
    float ss = x * x;
#pragma unroll
    for (int off = 16; off; off >>= 1) ss += __shfl_xor_sync(0xffffffffu, ss, off);
    __shared__ float red[4];
    __shared__ float sy[HD];
    if ((h & 31) == 0) red[h >> 5] = ss;
    __syncthreads();
    float tot = red[0] + red[1] + red[2] + red[3];
    float rinv = rsqrtf(tot * (1.0f / (float)HD) + 1e-6f);
    float y = w[h] * x * rinv;
    sy[h] = y;
    __syncthreads();

    int i = h & 63;
    float s = g_sin[t * 64 + i];
    float c = g_cos[t * 64 + i];
    float out;
    if (h < 64) out = y * c - sy[h + 64] * s;
    else        out = y * c + sy[h - 64] * s;
    p[h] = out;
}

// ---------------------------------------------------------------------------
// Flash attention on tf32 mma.sync. Block: 64 q-rows, 128 threads (4 warps,
// warp = 16 rows). s-tile = 32. Fragment-major smem for Q/K/V/P.
// ---------------------------------------------------------------------------
__global__ __launch_bounds__(128) void flash_mma(const float* __restrict__ Q,
                                                 const float* __restrict__ Kc,
                                                 const float* __restrict__ Vc,
                                                 float* __restrict__ O) {
    extern __shared__ float sm[];
    float* sQ = sm;            // 8192
    float* sK = sm + 8192;     // 4096
    float* sV = sm + 12288;    // 4096
    float* sP = sm + 16384;    // 2048

    const int tid = threadIdx.x;
    const int w = tid >> 5, lane = tid & 31;
    const int grp = lane >> 2, qd = lane & 3;
    const int b = blockIdx.z, n = blockIdx.y;
    const int qt = blockIdx.x << 6;
    const int kh = n >> 1;

    // Stage Q (fragment-major, tf32)
    {
        const float* Qb = Q + (((size_t)(b * Tt + qt)) * NQ + n) * HD;
#pragma unroll
        for (int u = 0; u < 16; u++) {
            int idx = tid + (u << 7);
            int r = idx >> 5, c4 = (idx & 31) << 2;
            float4 v = *(const float4*)(Qb + (size_t)r * (NQ * HD) + c4);
            float* pq = &sQ[((((r >> 4) << 4) + (c4 >> 3)) << 7) + ((r & 7) << 4) +
                            (((c4 >> 2) & 1) << 1) + ((r >> 3) & 1)];
            pq[0] = to_tf32(v.x); pq[4] = to_tf32(v.y);
            pq[8] = to_tf32(v.z); pq[12] = to_tf32(v.w);
        }
    }

    float oacc[16][4];
#pragma unroll
    for (int i = 0; i < 16; i++)
#pragma unroll
        for (int j = 0; j < 4; j++) oacc[i][j] = 0.f;
    float m0 = -1e30f, m1 = -1e30f, l0 = 0.f, l1 = 0.f;

    const float scale = 0.08838834764831845f;
    const int row0 = qt + (w << 4) + grp;
    const int row1 = row0 + 8;
    const int ntile = (qt >> 5) + 2;

    for (int st = 0; st < ntile; st++) {
        const int s0 = st << 5;
        __syncthreads();
        // Stage K and V (fragment-major, tf32)
        {
            const float* Kb = Kc + (((size_t)(b * Tt + s0)) * NK + kh) * HD;
            const float* Vb = Vc + (((size_t)(b * Tt + s0)) * NK + kh) * HD;
#pragma unroll
            for (int u = 0; u < 8; u++) {
                int idx = tid + (u << 7);
                int s = idx >> 5, h4 = (idx & 31) << 2;
                float4 vk = *(const float4*)(Kb + (size_t)s * (NK * HD) + h4);
                float* pk = &sK[((((s >> 3) << 4) + (h4 >> 3)) << 6) + ((s & 7) << 3) +
                                ((h4 >> 2) & 1)];
                pk[0] = to_tf32(vk.x); pk[2] = to_tf32(vk.y);
                pk[4] = to_tf32(vk.z); pk[6] = to_tf32(vk.w);
                float4 vv = *(const float4*)(Vb + (size_t)s * (NK * HD) + h4);
                float* pv = &sV[((((h4 >> 3) << 2) + (s >> 3)) << 6) +
                                ((((h4 & 7) << 2) + (s & 3)) << 1) + ((s >> 2) & 1)];
                pv[0] = to_tf32(vv.x); pv[8] = to_tf32(vv.y);
                pv[16] = to_tf32(vv.z); pv[24] = to_tf32(vv.w);
            }
        }
        __syncthreads();

        // S = Q @ K^T : per warp m16 x n32, k=128
        float sacc[4][4];
#pragma unroll
        for (int i = 0; i < 4; i++)
#pragma unroll
            for (int j = 0; j < 4; j++) sacc[i][j] = 0.f;
#pragma unroll
        for (int ko = 0; ko < 16; ko++) {
            uint4 af = *(const uint4*)&sQ[(((w << 4) + ko) << 7) + (lane << 2)];
#pragma unroll
            for (int nt = 0; nt < 4; nt++) {
                uint2 bf = *(const uint2*)&sK[(((nt << 4) + ko) << 6) + (lane << 1)];
                mma_tf32(sacc[nt][0], sacc[nt][1], sacc[nt][2], sacc[nt][3],
                         af.x, af.y, af.z, af.w, bf.x, bf.y);
            }
        }

        // Mask + online softmax (rows grp / grp+8, cols s0+nt*8+2qd{,+1})
        float mx0 = -1e30f, mx1 = -1e30f;
#pragma unroll
        for (int nt = 0; nt < 4; nt++) {
            int colb = s0 + (nt << 3) + (qd << 1);
            float v0 = sacc[nt][0] * scale;
            float v1 = sacc[nt][1] * scale;
            float v2 = sacc[nt][2] * scale;
            float v3 = sacc[nt][3] * scale;
            if (colb > row0)     v0 = -1e30f;
            if (colb + 1 > row0) v1 = -1e30f;
            if (colb > row1)     v2 = -1e30f;
            if (colb + 1 > row1) v3 = -1e30f;
            sacc[nt][0] = v0; sacc[nt][1] = v1; sacc[nt][2] = v2; sacc[nt][3] = v3;
            mx0 = fmaxf(mx0, fmaxf(v0, v1));
            mx1 = fmaxf(mx1, fmaxf(v2, v3));
        }
        mx0 = fmaxf(mx0, __shfl_xor_sync(0xffffffffu, mx0, 1));
        mx0 = fmaxf(mx0, __shfl_xor_sync(0xffffffffu, mx0, 2));
        mx1 = fmaxf(mx1, __shfl_xor_sync(0xffffffffu, mx1, 1));
        mx1 = fmaxf(mx1, __shfl_xor_sync(0xffffffffu, mx1, 2));
        float mn0 = fmaxf(m0, mx0), mn1 = fmaxf(m1, mx1);
        float a0 = __expf(m0 - mn0), a1 = __expf(m1 - mn1);
        m0 = mn0; m1 = mn1;
        float ps0 = 0.f, ps1 = 0.f;
#pragma unroll
        for (int nt = 0; nt < 4; nt++) {
            float p0 = __expf(sacc[nt][0] - m0);
            float p1 = __expf(sacc[nt][1] - m0);
            float p2 = __expf(sacc[nt][2] - m1);
            float p3 = __expf(sacc[nt][3] - m1);
            ps0 += p0 + p1; ps1 += p2 + p3;
            // store P in A-frag layout: mb=w, ko=nt, element (m, kk)
            int base = (((w << 2) + nt) << 7);
            int kk0 = (qd << 1), kk1 = kk0 + 1;
            sP[base + (grp << 4) + ((kk0 & 3) << 2) + ((kk0 >> 2) << 1) + 0] = to_tf32(p0);
            sP[base + (grp << 4) + ((kk1 & 3) << 2) + ((kk1 >> 2) << 1) + 0] = to_tf32(p1);
            sP[base + (grp << 4) + ((kk0 & 3) << 2) + ((kk0 >> 2) << 1) + 1] = to_tf32(p2);
            sP[base + (grp << 4) + ((kk1 & 3) << 2) + ((kk1 >> 2) << 1) + 1] = to_tf32(p3);
        }
        ps0 += __shfl_xor_sync(0xffffffffu, ps0, 1);
        ps0 += __shfl_xor_sync(0xffffffffu, ps0, 2);
        ps1 += __shfl_xor_sync(0xffffffffu, ps1, 1);
        ps1 += __shfl_xor_sync(0xffffffffu, ps1, 2);
        l0 = l0 * a0 + ps0;
        l1 = l1 * a1 + ps1;
#pragma unroll
        for (int nt = 0; nt < 16; nt++) {
            oacc[nt][0] *= a0; oacc[nt][1] *= a0;
            oacc[nt][2] *= a1; oacc[nt][3] *= a1;
        }
        __syncwarp();

        // O += P @ V : per warp m16 x n128, k=32
#pragma unroll
        for (int ko = 0; ko < 4; ko++) {
            uint4 af = *(const uint4*)&sP[(((w << 2) + ko) << 7) + (lane << 2)];
#pragma unroll
            for (int nt = 0; nt < 16; nt++) {
                uint2 bf = *(const uint2*)&sV[(((nt << 2) + ko) << 6) + (lane << 1)];
                mma_tf32(oacc[nt][0], oacc[nt][1], oacc[nt][2], oacc[nt][3],
                         af.x, af.y, af.z, af.w, bf.x, bf.y);
            }
        }
    }

    const float i0 = 1.0f / l0, i1 = 1.0f / l1;
    float* Ob0 = O + (((size_t)(b * Tt + row0)) * NQ + n) * HD;
    float* Ob1 = O + (((size_t)(b * Tt + row1)) * NQ + n) * HD;
#pragma unroll
    for (int nt = 0; nt < 16; nt++) {
        int col = (nt << 3) + (qd << 1);
        *(float2*)(Ob0 + col) = make_float2(oacc[nt][0] * i0, oacc[nt][1] * i0);
        *(float2*)(Ob1 + col) = make_float2(oacc[nt][2] * i1, oacc[nt][3] * i1);
    }
}

// ---------------------------------------------------------------------------
// Launch
// ---------------------------------------------------------------------------
extern "C" void kernel_launch(void* const* d_in, const int* in_sizes, int n_in,
                              void* d_out, int out_size) {
    (void)in_sizes; (void)n_in; (void)out_size;
    const float* x   = (const float*)d_in[0];
    const float* qw  = (const float*)d_in[1];
    const float* kw  = (const float*)d_in[2];
    const float* vw  = (const float*)d_in[3];
    const float* ow  = (const float*)d_in[4];
    const float* qnw = (const float*)d_in[5];
    const float* knw = (const float*)d_in[6];
    float* out = (float*)d_out;

    float *gq, *gk, *gv, *go;
    cudaGetSymbolAddress((void**)&gq, g_q);
    cudaGetSymbolAddress((void**)&gk, g_k);
    cudaGetSymbolAddress((void**)&gv, g_v);
    cudaGetSymbolAddress((void**)&go, g_o);

    const int M = Bb * Tt; // 4096

    rope_table<<<(Tt * 64 + 255) / 256, 256>>>();

    gemm_tf32<<<dim3((NQ * HD) / 128, M / 128), 256>>>(x, qw, gq, M, NQ * HD, Dd);
    gemm_tf32<<<dim3((NK * HD) / 128, M / 128), 256>>>(x, kw, gk, M, NK * HD, Dd);
    gemm_tf32<<<dim3((NK * HD) / 128, M / 128), 256>>>(x, vw, gv, M, NK * HD, Dd);

    rms_rope<<<M * NQ, 128>>>(gq, qnw, NQ);
    rms_rope<<<M * NK, 128>>>(gk, knw, NK);

    size_t smem = (size_t)18432 * sizeof(float); // 73728 B
    cudaFuncSetAttribute(flash_mma, cudaFuncAttributeMaxDynamicSharedMemorySize, (int)smem);
    flash_mma<<<dim3(Tt / 64, NQ, Bb), 128, smem>>>(gq, gk, gv, go);

    gemm_tf32<<<dim3(Dd / 128, M / 128), 256>>>(go, ow, out, M, Dd, NQ * HD);
}

// round 5
// speedup vs baseline: 2.5790x; 2.5790x over previous
#include <cuda_runtime.h>
#include <math.h>
#include <stdint.h>

// Problem constants (fixed by setup_inputs)
#define Bb 2
#define Tt 2048
#define Dd 2048
#define NQ 16
#define NK 8
#define HD 128
#define MROWS (Bb * Tt)

// Scratch (device globals: allocation-free rule)
__device__ float g_q[(size_t)MROWS * NQ * HD];      // 32 MB
__device__ float g_k[(size_t)MROWS * NK * HD];      // 16 MB
__device__ float g_vt[(size_t)Bb * NK * HD * Tt];   // 16 MB (V transposed: [b][kh][h][t])
__device__ float g_o[(size_t)MROWS * NQ * HD];      // 32 MB
__device__ float g_wtq[2048 * 2048];                // q_w^T  [NH][D]
__device__ float g_wtk[1024 * 2048];                // k_w^T  [KH*H][D]
__device__ float g_wtv[1024 * 2048];                // v_w^T
__device__ float g_wto[2048 * 2048];                // o_w^T  [D][NH]
__device__ float g_sin[Tt * 64];
__device__ float g_cos[Tt * 64];

__device__ __forceinline__ float to_tf32(float x) {
    uint32_t r;
    asm("cvt.rna.tf32.f32 %0, %1;" : "=r"(r) : "f"(x));
    return __uint_as_float(r);
}

__device__ __forceinline__ float4 f4_tf32(float4 v) {
    return make_float4(to_tf32(v.x), to_tf32(v.y), to_tf32(v.z), to_tf32(v.w));
}

__device__ __forceinline__ void mma_tf32(float* d,
                                         uint32_t a0, uint32_t a1, uint32_t a2, uint32_t a3,
                                         uint32_t b0, uint32_t b1) {
    asm volatile(
        "mma.sync.aligned.m16n8k8.row.col.f32.tf32.tf32.f32 "
        "{%0,%1,%2,%3}, {%4,%5,%6,%7}, {%8,%9}, {%0,%1,%2,%3};"
        : "+f"(d[0]), "+f"(d[1]), "+f"(d[2]), "+f"(d[3])
        : "r"(a0), "r"(a1), "r"(a2), "r"(a3), "r"(b0), "r"(b1));
}

// ldmatrix x4 on 32-bit (tf32) data: each 8x8xb16-pair matrix = 8x4 of 32-bit.
__device__ __forceinline__ void ldsm4(uint32_t* r, const float* p) {
    uint32_t a = (uint32_t)__cvta_generic_to_shared(p);
    asm volatile("ldmatrix.sync.aligned.m8n8.x4.shared.b16 {%0,%1,%2,%3}, [%4];"
                 : "=r"(r[0]), "=r"(r[1]), "=r"(r[2]), "=r"(r[3]) : "r"(a));
}

// ---------------------------------------------------------------------------
// 32x32 tiled transpose: in[R][C] -> out[C][R]
// ---------------------------------------------------------------------------
__global__ __launch_bounds__(256) void transpose_k(const float* __restrict__ in,
                                                   float* __restrict__ out,
                                                   int R, int C) {
    __shared__ float t[32][33];
    const int bx = blockIdx.x << 5, by = blockIdx.y << 5;
    const int tx = threadIdx.x & 31, ty = threadIdx.x >> 5; // ty 0..7
#pragma unroll
    for (int i = 0; i < 32; i += 8)
        t[ty + i][tx] = in[(size_t)(by + ty + i) * C + bx + tx];
    __syncthreads();
#pragma unroll
    for (int i = 0; i < 32; i += 8)
        out[(size_t)(bx + ty + i) * R + by + tx] = t[tx][ty + i];
}

// ---------------------------------------------------------------------------
// tf32 GEMM: C[M,N] = A[M,K] @ BT[N,K]^T. Row-major fp32. Block 128x128x16,
// 256 threads, 8 warps (2m x 4n), warp tile 64x32. ldmatrix fragment loads,
// smem rows: 16 floats padded to 20 (odd 16B-chunk stride -> conflict-free).
// vt==1: write output transposed into g_vt layout [b][kh][h][t].
// ---------------------------------------------------------------------------
__global__ __launch_bounds__(256) void gemm_v3(const float* __restrict__ A,
                                               const float* __restrict__ BT,
                                               float* __restrict__ C,
                                               int M, int N, int K, int vt) {
    __shared__ float sA[2][128 * 20];
    __shared__ float sB[2][128 * 20];
    const int tid = threadIdx.x;
    const int bm = blockIdx.y << 7, bn = blockIdx.x << 7;
    const int warp = tid >> 5, lane = tid & 31;
    const int wm = (warp >> 2) << 6, wn = (warp & 3) << 5;
    const int grp = lane >> 2, qd = lane & 3;

    const int rs = tid >> 2;           // 0..63 (+64 for u=1)
    const int cs = (tid & 3) << 2;     // 0,4,8,12

    float acc[4][4][4];
#pragma unroll
    for (int i = 0; i < 4; i++)
#pragma unroll
        for (int j = 0; j < 4; j++)
#pragma unroll
            for (int r = 0; r < 4; r++) acc[i][j][r] = 0.f;

    float4 pa[2], pb[2];
#pragma unroll
    for (int u = 0; u < 2; u++) {
        pa[u] = *(const float4*)(A + (size_t)(bm + rs + u * 64) * K + cs);
        pb[u] = *(const float4*)(BT + (size_t)(bn + rs + u * 64) * K + cs);
    }
#pragma unroll
    for (int u = 0; u < 2; u++) {
        *(float4*)&sA[0][(rs + u * 64) * 20 + cs] = f4_tf32(pa[u]);
        *(float4*)&sB[0][(rs + u * 64) * 20 + cs] = f4_tf32(pb[u]);
    }
    __syncthreads();

    const int nkt = K >> 4;
    // ldmatrix lane addressing
    const int a_row = ((lane >> 3) & 1) * 8 + (lane & 7);
    const int a_csub = ((lane >> 4) & 1) * 4;
    const int b_row = lane & 7;
    const int b_col = ((lane >> 3) & 3) * 4;

    for (int kt = 0; kt < nkt; kt++) {
        const int buf = kt & 1;
        if (kt + 1 < nkt) {
            const int k0 = (kt + 1) << 4;
#pragma unroll
            for (int u = 0; u < 2; u++) {
                pa[u] = *(const float4*)(A + (size_t)(bm + rs + u * 64) * K + k0 + cs);
                pb[u] = *(const float4*)(BT + (size_t)(bn + rs + u * 64) * K + k0 + cs);
            }
        }
        // B fragments for the whole k16 tile: per nt one x4 (n8 x k16)
        uint32_t bfr[4][4];
#pragma unroll
        for (int nt = 0; nt < 4; nt++)
            ldsm4(bfr[nt], &sB[buf][(wn + nt * 8 + b_row) * 20 + b_col]);
#pragma unroll
        for (int ko = 0; ko < 2; ko++) {
            uint32_t af[4][4];
#pragma unroll
            for (int mt = 0; mt < 4; mt++)
                ldsm4(af[mt], &sA[buf][(wm + mt * 16 + a_row) * 20 + ko * 8 + a_csub]);
#pragma unroll
            for (int mt = 0; mt < 4; mt++)
#pragma unroll
                for (int nt = 0; nt < 4; nt++)
                    mma_tf32(acc[mt][nt], af[mt][0], af[mt][1], af[mt][2], af[mt][3],
                             bfr[nt][ko * 2], bfr[nt][ko * 2 + 1]);
        }
        if (kt + 1 < nkt) {
            const int nb = buf ^ 1;
#pragma unroll
            for (int u = 0; u < 2; u++) {
                *(float4*)&sA[nb][(rs + u * 64) * 20 + cs] = f4_tf32(pa[u]);
                *(float4*)&sB[nb][(rs + u * 64) * 20 + cs] = f4_tf32(pb[u]);
            }
        }
        __syncthreads();
    }

    if (!vt) {
#pragma unroll
        for (int mt = 0; mt < 4; mt++)
#pragma unroll
            for (int nt = 0; nt < 4; nt++) {
                int row = bm + wm + (mt << 4) + grp;
                int col = bn + wn + (nt << 3) + (qd << 1);
                *(float2*)(C + (size_t)row * N + col) =
                    make_float2(acc[mt][nt][0], acc[mt][nt][1]);
                *(float2*)(C + (size_t)(row + 8) * N + col) =
                    make_float2(acc[mt][nt][2], acc[mt][nt][3]);
            }
    } else {
        // transposed store into [b][kh][h][t]; M row = b*Tt + t, col = kh*HD + h
#pragma unroll
        for (int mt = 0; mt < 4; mt++)
#pragma unroll
            for (int nt = 0; nt < 4; nt++) {
                int row = bm + wm + (mt << 4) + grp;
                int col = bn + wn + (nt << 3) + (qd << 1);
                int b = row >> 11, t = row & 2047;
                size_t base0 = ((size_t)b * NK * HD + col) * Tt + t;      // (col -> kh,h fused)
                size_t base1 = ((size_t)b * NK * HD + col + 1) * Tt + t;
                C[base0] = acc[mt][nt][0];
                C[base1] = acc[mt][nt][1];
                C[base0 + 8] = acc[mt][nt][2];
                C[base1 + 8] = acc[mt][nt][3];
            }
    }
}

// ---------------------------------------------------------------------------
// RoPE table
// ---------------------------------------------------------------------------
__global__ __launch_bounds__(256) void rope_table() {
    int idx = blockIdx.x * 256 + threadIdx.x;
    if (idx >= Tt * 64) return;
    int t = idx >> 6, i = idx & 63;
    double ang = (double)t * exp(-0.21586735246819178 * (double)i);
    double s, c;
    sincos(ang, &s, &c);
    g_sin[idx] = (float)s;
    g_cos[idx] = (float)c;
}

// ---------------------------------------------------------------------------
// Fused RMSNorm + RoPE (table-based)
// ---------------------------------------------------------------------------
__global__ __launch_bounds__(128) void rms_rope(float* __restrict__ buf,
                                                const float* __restrict__ w,
                                                int heads) {
    const int idx = blockIdx.x;
    const int t = (idx / heads) % Tt;
    float* p = buf + (size_t)idx * HD;
    const int h = threadIdx.x;

    float x = p[h];
    float ss = x * x;
#pragma unroll
    for (int off = 16; off; off >>= 1) ss += __shfl_xor_sync(0xffffffffu, ss, off);
    __shared__ float red[4];
    __shared__ float sy[HD];
    if ((h & 31) == 0) red[h >> 5] = ss;
    __syncthreads();
    float tot = red[0] + red[1] + red[2] + red[3];
    float rinv = rsqrtf(tot * (1.0f / (float)HD) + 1e-6f);
    float y = w[h] * x * rinv;
    sy[h] = y;
    __syncthreads();

    int i = h & 63;
    float s = g_sin[t * 64 + i];
    float c = g_cos[t * 64 + i];
    float out;
    if (h < 64) out = y * c - sy[h + 64] * s;
    else        out = y * c + sy[h - 64] * s;
    p[h] = out;
}

// ---------------------------------------------------------------------------
// Flash attention, tf32 mma + ldmatrix. 128 threads (4 warps), q-tile 64
// (warp = 16 rows), s-tile 32. smem rows padded to odd 16B-chunk strides.
//   sQ  [64][132], sK [32][132], sVT [128][36], sP [64][36]
// ---------------------------------------------------------------------------
__global__ __launch_bounds__(128) void flash_v3(const float* __restrict__ Q,
                                                const float* __restrict__ Kc,
                                                const float* __restrict__ VT,
                                                float* __restrict__ O) {
    extern __shared__ float sm[];
    float* sQ = sm;               // 64*132  = 8448
    float* sK = sQ + 8448;        // 32*132  = 4224
    float* sVT = sK + 4224;       // 128*36  = 4608
    float* sP = sVT + 4608;       // 64*36   = 2304

    const int tid = threadIdx.x;
    const int w = tid >> 5, lane = tid & 31;
    const int grp = lane >> 2, qd = lane & 3;
    const int b = blockIdx.z, n = blockIdx.y;
    const int qt = blockIdx.x << 6;
    const int kh = n >> 1;

    const int a_row = ((lane >> 3) & 1) * 8 + (lane & 7);
    const int a_csub = ((lane >> 4) & 1) * 4;
    const int b_row = lane & 7;
    const int b_col = ((lane >> 3) & 3) * 4;

    // Stage Q [64][128] -> sQ stride 132
    {
        const float* Qb = Q + ((size_t)(b * Tt + qt) * NQ + n) * HD;
#pragma unroll
        for (int u = 0; u < 16; u++) {
            int idx = tid + (u << 7);
            int r = idx >> 5, c = (idx & 31) << 2;
            float4 v = *(const float4*)(Qb + (size_t)r * (NQ * HD) + c);
            *(float4*)&sQ[r * 132 + c] = f4_tf32(v);
        }
    }

    float oacc[16][4];
#pragma unroll
    for (int i = 0; i < 16; i++)
#pragma unroll
        for (int j = 0; j < 4; j++) oacc[i][j] = 0.f;
    float m0 = -1e30f, m1 = -1e30f, l0 = 0.f, l1 = 0.f;

    const float scale = 0.08838834764831845f;
    const int row0 = qt + (w << 4) + grp;
    const int row1 = row0 + 8;
    const int ntile = (qt >> 5) + 2;

    for (int st = 0; st < ntile; st++) {
        const int s0 = st << 5;
        __syncthreads();
        // Stage K [32][128] and VT [128][32]
        {
            const float* Kb = Kc + ((size_t)(b * Tt + s0) * NK + kh) * HD;
            const float* Vb = VT + ((size_t)(b * NK + kh) * HD) * Tt + s0;
#pragma unroll
            for (int u = 0; u < 8; u++) {
                int idx = tid + (u << 7);
                int r = idx >> 5, c = (idx & 31) << 2;
                float4 vk = *(const float4*)(Kb + (size_t)r * (NK * HD) + c);
                *(float4*)&sK[r * 132 + c] = f4_tf32(vk);
                int h = idx >> 3, cv = (idx & 7) << 2;
                float4 vv = *(const float4*)(Vb + (size_t)h * Tt + cv);
                *(float4*)&sVT[h * 36 + cv] = f4_tf32(vv);
            }
        }
        __syncthreads();

        // S = Q @ K^T : warp m16 x n32, k=128
        float sacc[4][4];
#pragma unroll
        for (int i = 0; i < 4; i++)
#pragma unroll
            for (int j = 0; j < 4; j++) sacc[i][j] = 0.f;
#pragma unroll
        for (int kp = 0; kp < 8; kp++) {
            uint32_t af0[4], af1[4];
            ldsm4(af0, &sQ[((w << 4) + a_row) * 132 + (kp << 4) + a_csub]);
            ldsm4(af1, &sQ[((w << 4) + a_row) * 132 + (kp << 4) + 8 + a_csub]);
#pragma unroll
            for (int nt = 0; nt < 4; nt++) {
                uint32_t bf[4];
                ldsm4(bf, &sK[((nt << 3) + b_row) * 132 + (kp << 4) + b_col]);
                mma_tf32(sacc[nt], af0[0], af0[1], af0[2], af0[3], bf[0], bf[1]);
                mma_tf32(sacc[nt], af1[0], af1[1], af1[2], af1[3], bf[2], bf[3]);
            }
        }

        // Mask + online softmax
        float mx0 = -1e30f, mx1 = -1e30f;
#pragma unroll
        for (int nt = 0; nt < 4; nt++) {
            int colb = s0 + (nt << 3) + (qd << 1);
            float v0 = sacc[nt][0] * scale;
            float v1 = sacc[nt][1] * scale;
            float v2 = sacc[nt][2] * scale;
            float v3 = sacc[nt][3] * scale;
            if (colb > row0)     v0 = -1e30f;
            if (colb + 1 > row0) v1 = -1e30f;
            if (colb > row1)     v2 = -1e30f;
            if (colb + 1 > row1) v3 = -1e30f;
            sacc[nt][0] = v0; sacc[nt][1] = v1; sacc[nt][2] = v2; sacc[nt][3] = v3;
            mx0 = fmaxf(mx0, fmaxf(v0, v1));
            mx1 = fmaxf(mx1, fmaxf(v2, v3));
        }
        mx0 = fmaxf(mx0, __shfl_xor_sync(0xffffffffu, mx0, 1));
        mx0 = fmaxf(mx0, __shfl_xor_sync(0xffffffffu, mx0, 2));
        mx1 = fmaxf(mx1, __shfl_xor_sync(0xffffffffu, mx1, 1));
        mx1 = fmaxf(mx1, __shfl_xor_sync(0xffffffffu, mx1, 2));
        float mn0 = fmaxf(m0, mx0), mn1 = fmaxf(m1, mx1);
        float a0 = __expf(m0 - mn0), a1 = __expf(m1 - mn1);
        m0 = mn0; m1 = mn1;
        float ps0 = 0.f, ps1 = 0.f;
#pragma unroll
        for (int nt = 0; nt < 4; nt++) {
            float p0 = __expf(sacc[nt][0] - m0);
            float p1 = __expf(sacc[nt][1] - m0);
            float p2 = __expf(sacc[nt][2] - m1);
            float p3 = __expf(sacc[nt][3] - m1);
            ps0 += p0 + p1; ps1 += p2 + p3;
            int col = (nt << 3) + (qd << 1);
            *(float2*)&sP[((w << 4) + grp) * 36 + col] =
                make_float2(to_tf32(p0), to_tf32(p1));
            *(float2*)&sP[((w << 4) + grp + 8) * 36 + col] =
                make_float2(to_tf32(p2), to_tf32(p3));
        }
        ps0 += __shfl_xor_sync(0xffffffffu, ps0, 1);
        ps0 += __shfl_xor_sync(0xffffffffu, ps0, 2);
        ps1 += __shfl_xor_sync(0xffffffffu, ps1, 1);
        ps1 += __shfl_xor_sync(0xffffffffu, ps1, 2);
        l0 = l0 * a0 + ps0;
        l1 = l1 * a1 + ps1;
#pragma unroll
        for (int nt = 0; nt < 16; nt++) {
            oacc[nt][0] *= a0; oacc[nt][1] *= a0;
            oacc[nt][2] *= a1; oacc[nt][3] *= a1;
        }
        __syncwarp();

        // O += P @ V : warp m16 x n128, k=32
#pragma unroll
        for (int kp = 0; kp < 2; kp++) {
            uint32_t af0[4], af1[4];
            ldsm4(af0, &sP[((w << 4) + a_row) * 36 + (kp << 4) + a_csub]);
            ldsm4(af1, &sP[((w << 4) + a_row) * 36 + (kp << 4) + 8 + a_csub]);
#pragma unroll
            for (int nt = 0; nt < 16; nt++) {
                uint32_t bf[4];
                ldsm4(bf, &sVT[((nt << 3) + b_row) * 36 + (kp << 4) + b_col]);
                mma_tf32(oacc[nt], af0[0], af0[1], af0[2], af0[3], bf[0], bf[1]);
                mma_tf32(oacc[nt], af1[0], af1[1], af1[2], af1[3], bf[2], bf[3]);
            }
        }
    }

    const float i0 = 1.0f / l0, i1 = 1.0f / l1;
    float* Ob0 = O + ((size_t)(b * Tt + row0) * NQ + n) * HD;
    float* Ob1 = O + ((size_t)(b * Tt + row1) * NQ + n) * HD;
#pragma unroll
    for (int nt = 0; nt < 16; nt++) {
        int col = (nt << 3) + (qd << 1);
        *(float2*)(Ob0 + col) = make_float2(oacc[nt][0] * i0, oacc[nt][1] * i0);
        *(float2*)(Ob1 + col) = make_float2(oacc[nt][2] * i1, oacc[nt][3] * i1);
    }
}

// ---------------------------------------------------------------------------
// Launch
// ---------------------------------------------------------------------------
extern "C" void kernel_launch(void* const* d_in, const int* in_sizes, int n_in,
                              void* d_out, int out_size) {
    (void)in_sizes; (void)n_in; (void)out_size;
    const float* x   = (const float*)d_in[0];
    const float* qw  = (const float*)d_in[1];
    const float* kw  = (const float*)d_in[2];
    const float* vw  = (const float*)d_in[3];
    const float* ow  = (const float*)d_in[4];
    const float* qnw = (const float*)d_in[5];
    const float* knw = (const float*)d_in[6];
    float* out = (float*)d_out;

    float *gq, *gk, *gvt, *go, *wtq, *wtk, *wtv, *wto;
    cudaGetSymbolAddress((void**)&gq, g_q);
    cudaGetSymbolAddress((void**)&gk, g_k);
    cudaGetSymbolAddress((void**)&gvt, g_vt);
    cudaGetSymbolAddress((void**)&go, g_o);
    cudaGetSymbolAddress((void**)&wtq, g_wtq);
    cudaGetSymbolAddress((void**)&wtk, g_wtk);
    cudaGetSymbolAddress((void**)&wtv, g_wtv);
    cudaGetSymbolAddress((void**)&wto, g_wto);

    const int M = MROWS; // 4096
    const int NH = NQ * HD;  // 2048
    const int KHH = NK * HD; // 1024

    rope_table<<<(Tt * 64 + 255) / 256, 256>>>();

    // Weight transposes: in[R][C] -> out[C][R], grid (C/32, R/32)
    transpose_k<<<dim3(NH / 32, Dd / 32), 256>>>(qw, wtq, Dd, NH);
    transpose_k<<<dim3(KHH / 32, Dd / 32), 256>>>(kw, wtk, Dd, KHH);
    transpose_k<<<dim3(KHH / 32, Dd / 32), 256>>>(vw, wtv, Dd, KHH);
    transpose_k<<<dim3(Dd / 32, NH / 32), 256>>>(ow, wto, NH, Dd);

    // Projections
    gemm_v3<<<dim3(NH / 128, M / 128), 256>>>(x, wtq, gq, M, NH, Dd, 0);
    gemm_v3<<<dim3(KHH / 128, M / 128), 256>>>(x, wtk, gk, M, KHH, Dd, 0);
    gemm_v3<<<dim3(KHH / 128, M / 128), 256>>>(x, wtv, gvt, M, KHH, Dd, 1);

    // RMSNorm + RoPE (in place)
    rms_rope<<<M * NQ, 128>>>(gq, qnw, NQ);
    rms_rope<<<M * NK, 128>>>(gk, knw, NK);

    // Flash attention
    size_t smem = (size_t)19584 * sizeof(float); // 78336 B
    cudaFuncSetAttribute(flash_v3, cudaFuncAttributeMaxDynamicSharedMemorySize, (int)smem);
    flash_v3<<<dim3(Tt / 64, NQ, Bb), 128, smem>>>(gq, gk, gvt, go);

    // Output projection
    gemm_v3<<<dim3(Dd / 128, M / 128), 256>>>(go, wto, out, M, Dd, NH, 0);
}

// round 6
// speedup vs baseline: 2.6036x; 1.0095x over previous
#include <cuda_runtime.h>
#include <math.h>
#include <stdint.h>

// Problem constants (fixed by setup_inputs)
#define Bb 2
#define Tt 2048
#define Dd 2048
#define NQ 16
#define NK 8
#define HD 128
#define MROWS (Bb * Tt)

// Scratch (device globals: allocation-free rule)
__device__ float g_q[(size_t)MROWS * NQ * HD];      // 32 MB
__device__ float g_k[(size_t)MROWS * NK * HD];      // 16 MB
__device__ float g_vt[(size_t)Bb * NK * HD * Tt];   // 16 MB (V transposed: [b][kh][h][t])
__device__ float g_o[(size_t)MROWS * NQ * HD];      // 32 MB
__device__ float g_wtq[2048 * 2048];                // q_w^T  [NH][D]
__device__ float g_wtk[1024 * 2048];                // k_w^T  [KH*H][D]
__device__ float g_wtv[1024 * 2048];                // v_w^T
__device__ float g_wto[2048 * 2048];                // o_w^T  [D][NH]
__device__ float g_sin[Tt * 64];
__device__ float g_cos[Tt * 64];

__device__ __forceinline__ float to_tf32(float x) {
    uint32_t r;
    asm("cvt.rna.tf32.f32 %0, %1;" : "=r"(r) : "f"(x));
    return __uint_as_float(r);
}

__device__ __forceinline__ float4 f4_tf32(float4 v) {
    return make_float4(to_tf32(v.x), to_tf32(v.y), to_tf32(v.z), to_tf32(v.w));
}

__device__ __forceinline__ void mma_tf32(float* d,
                                         uint32_t a0, uint32_t a1, uint32_t a2, uint32_t a3,
                                         uint32_t b0, uint32_t b1) {
    asm volatile(
        "mma.sync.aligned.m16n8k8.row.col.f32.tf32.tf32.f32 "
        "{%0,%1,%2,%3}, {%4,%5,%6,%7}, {%8,%9}, {%0,%1,%2,%3};"
        : "+f"(d[0]), "+f"(d[1]), "+f"(d[2]), "+f"(d[3])
        : "r"(a0), "r"(a1), "r"(a2), "r"(a3), "r"(b0), "r"(b1));
}

// ldmatrix x4 on 32-bit (tf32) data: each 8x8xb16-pair matrix = 8x4 of 32-bit.
__device__ __forceinline__ void ldsm4(uint32_t* r, const float* p) {
    uint32_t a = (uint32_t)__cvta_generic_to_shared(p);
    asm volatile("ldmatrix.sync.aligned.m8n8.x4.shared.b16 {%0,%1,%2,%3}, [%4];"
                 : "=r"(r[0]), "=r"(r[1]), "=r"(r[2]), "=r"(r[3]) : "r"(a));
}

// ---------------------------------------------------------------------------
// 32x32 tiled transpose: in[R][C] -> out[C][R]
// ---------------------------------------------------------------------------
__global__ __launch_bounds__(256) void transpose_k(const float* __restrict__ in,
                                                   float* __restrict__ out,
                                                   int R, int C) {
    __shared__ float t[32][33];
    const int bx = blockIdx.x << 5, by = blockIdx.y << 5;
    const int tx = threadIdx.x & 31, ty = threadIdx.x >> 5; // ty 0..7
#pragma unroll
    for (int i = 0; i < 32; i += 8)
        t[ty + i][tx] = in[(size_t)(by + ty + i) * C + bx + tx];
    __syncthreads();
#pragma unroll
    for (int i = 0; i < 32; i += 8)
        out[(size_t)(bx + ty + i) * R + by + tx] = t[tx][ty + i];
}

// ---------------------------------------------------------------------------
// tf32 GEMM: C[M,N] = A[M,K] @ BT[N,K]^T. Row-major fp32. Block 128x128x16,
// 256 threads, 8 warps (2m x 4n), warp tile 64x32. ldmatrix fragment loads.
// vt==1: write output transposed into g_vt layout [b][kh][h][t].
// ---------------------------------------------------------------------------
__global__ __launch_bounds__(256) void gemm_v3(const float* __restrict__ A,
                                               const float* __restrict__ BT,
                                               float* __restrict__ C,
                                               int M, int N, int K, int vt) {
    __shared__ float sA[2][128 * 20];
    __shared__ float sB[2][128 * 20];
    const int tid = threadIdx.x;
    const int bm = blockIdx.y << 7, bn = blockIdx.x << 7;
    const int warp = tid >> 5, lane = tid & 31;
    const int wm = (warp >> 2) << 6, wn = (warp & 3) << 5;
    const int grp = lane >> 2, qd = lane & 3;

    const int rs = tid >> 2;
    const int cs = (tid & 3) << 2;

    float acc[4][4][4];
#pragma unroll
    for (int i = 0; i < 4; i++)
#pragma unroll
        for (int j = 0; j < 4; j++)
#pragma unroll
            for (int r = 0; r < 4; r++) acc[i][j][r] = 0.f;

    float4 pa[2], pb[2];
#pragma unroll
    for (int u = 0; u < 2; u++) {
        pa[u] = *(const float4*)(A + (size_t)(bm + rs + u * 64) * K + cs);
        pb[u] = *(const float4*)(BT + (size_t)(bn + rs + u * 64) * K + cs);
    }
#pragma unroll
    for (int u = 0; u < 2; u++) {
        *(float4*)&sA[0][(rs + u * 64) * 20 + cs] = f4_tf32(pa[u]);
        *(float4*)&sB[0][(rs + u * 64) * 20 + cs] = f4_tf32(pb[u]);
    }
    __syncthreads();

    const int nkt = K >> 4;
    const int a_row = ((lane >> 3) & 1) * 8 + (lane & 7);
    const int a_csub = ((lane >> 4) & 1) * 4;
    const int b_row = lane & 7;
    const int b_col = ((lane >> 3) & 3) * 4;

    for (int kt = 0; kt < nkt; kt++) {
        const int buf = kt & 1;
        if (kt + 1 < nkt) {
            const int k0 = (kt + 1) << 4;
#pragma unroll
            for (int u = 0; u < 2; u++) {
                pa[u] = *(const float4*)(A + (size_t)(bm + rs + u * 64) * K + k0 + cs);
                pb[u] = *(const float4*)(BT + (size_t)(bn + rs + u * 64) * K + k0 + cs);
            }
        }
        uint32_t bfr[4][4];
#pragma unroll
        for (int nt = 0; nt < 4; nt++)
            ldsm4(bfr[nt], &sB[buf][(wn + nt * 8 + b_row) * 20 + b_col]);
#pragma unroll
        for (int ko = 0; ko < 2; ko++) {
            uint32_t af[4][4];
#pragma unroll
            for (int mt = 0; mt < 4; mt++)
                ldsm4(af[mt], &sA[buf][(wm + mt * 16 + a_row) * 20 + ko * 8 + a_csub]);
#pragma unroll
            for (int mt = 0; mt < 4; mt++)
#pragma unroll
                for (int nt = 0; nt < 4; nt++)
                    mma_tf32(acc[mt][nt], af[mt][0], af[mt][1], af[mt][2], af[mt][3],
                             bfr[nt][ko * 2], bfr[nt][ko * 2 + 1]);
        }
        if (kt + 1 < nkt) {
            const int nb = buf ^ 1;
#pragma unroll
            for (int u = 0; u < 2; u++) {
                *(float4*)&sA[nb][(rs + u * 64) * 20 + cs] = f4_tf32(pa[u]);
                *(float4*)&sB[nb][(rs + u * 64) * 20 + cs] = f4_tf32(pb[u]);
            }
        }
        __syncthreads();
    }

    if (!vt) {
#pragma unroll
        for (int mt = 0; mt < 4; mt++)
#pragma unroll
            for (int nt = 0; nt < 4; nt++) {
                int row = bm + wm + (mt << 4) + grp;
                int col = bn + wn + (nt << 3) + (qd << 1);
                *(float2*)(C + (size_t)row * N + col) =
                    make_float2(acc[mt][nt][0], acc[mt][nt][1]);
                *(float2*)(C + (size_t)(row + 8) * N + col) =
                    make_float2(acc[mt][nt][2], acc[mt][nt][3]);
            }
    } else {
#pragma unroll
        for (int mt = 0; mt < 4; mt++)
#pragma unroll
            for (int nt = 0; nt < 4; nt++) {
                int row = bm + wm + (mt << 4) + grp;
                int col = bn + wn + (nt << 3) + (qd << 1);
                int b = row >> 11, t = row & 2047;
                size_t base0 = ((size_t)b * NK * HD + col) * Tt + t;
                size_t base1 = ((size_t)b * NK * HD + col + 1) * Tt + t;
                C[base0] = acc[mt][nt][0];
                C[base1] = acc[mt][nt][1];
                C[base0 + 8] = acc[mt][nt][2];
                C[base1 + 8] = acc[mt][nt][3];
            }
    }
}

// ---------------------------------------------------------------------------
// RoPE table
// ---------------------------------------------------------------------------
__global__ __launch_bounds__(256) void rope_table() {
    int idx = blockIdx.x * 256 + threadIdx.x;
    if (idx >= Tt * 64) return;
    int t = idx >> 6, i = idx & 63;
    double ang = (double)t * exp(-0.21586735246819178 * (double)i);
    double s, c;
    sincos(ang, &s, &c);
    g_sin[idx] = (float)s;
    g_cos[idx] = (float)c;
}

// ---------------------------------------------------------------------------
// Fused RMSNorm + RoPE (table-based)
// ---------------------------------------------------------------------------
__global__ __launch_bounds__(128) void rms_rope(float* __restrict__ buf,
                                                const float* __restrict__ w,
                                                int heads) {
    const int idx = blockIdx.x;
    const int t = (idx / heads) % Tt;
    float* p = buf + (size_t)idx * HD;
    const int h = threadIdx.x;

    float x = p[h];
    float ss = x * x;
#pragma unroll
    for (int off = 16; off; off >>= 1) ss += __shfl_xor_sync(0xffffffffu, ss, off);
    __shared__ float red[4];
    __shared__ float sy[HD];
    if ((h & 31) == 0) red[h >> 5] = ss;
    __syncthreads();
    float tot = red[0] + red[1] + red[2] + red[3];
    float rinv = rsqrtf(tot * (1.0f / (float)HD) + 1e-6f);
    float y = w[h] * x * rinv;
    sy[h] = y;
    __syncthreads();

    int i = h & 63;
    float s = g_sin[t * 64 + i];
    float c = g_cos[t * 64 + i];
    float out;
    if (h < 64) out = y * c - sy[h + 64] * s;
    else        out = y * c + sy[h - 64] * s;
    p[h] = out;
}

// ---------------------------------------------------------------------------
// Flash attention v4: tf32 mma + ldmatrix. 256 threads (8 warps), q-tile 128
// (warp = 16 rows, Q fragments held in registers), s-tile 32.
//   sK  [32][132] = 4224 f   (also used as Q staging buffer, 32-row chunks)
//   sVT [128][36] = 4608 f
//   sP  8 x [16][36] = 4608 f (per-warp)
// ---------------------------------------------------------------------------
__global__ __launch_bounds__(256) void flash_v4(const float* __restrict__ Q,
                                                const float* __restrict__ Kc,
                                                const float* __restrict__ VT,
                                                float* __restrict__ O) {
    extern __shared__ float sm[];
    float* sK = sm;               // 4224
    float* sVT = sK + 4224;       // 4608
    float* sP = sVT + 4608;       // 4608

    const int tid = threadIdx.x;
    const int w = tid >> 5, lane = tid & 31;
    const int grp = lane >> 2, qd = lane & 3;
    const int b = blockIdx.z, n = blockIdx.y;
    const int qt = blockIdx.x << 7;   // 128-row q tile
    const int kh = n >> 1;

    const int a_row = ((lane >> 3) & 1) * 8 + (lane & 7);
    const int a_csub = ((lane >> 4) & 1) * 4;
    const int b_row = lane & 7;
    const int b_col = ((lane >> 3) & 3) * 4;

    // --- Load Q fragments into registers, staged through sK in 32-row chunks.
    uint32_t qf[8][8];
    {
        const float* Qb = Q + ((size_t)(b * Tt + qt) * NQ + n) * HD;
#pragma unroll
        for (int c = 0; c < 4; c++) {
#pragma unroll
            for (int u = 0; u < 4; u++) {
                int idx = tid + (u << 8);
                int r = idx >> 5, cc = (idx & 31) << 2;
                float4 v = *(const float4*)(Qb + (size_t)(c * 32 + r) * (NQ * HD) + cc);
                *(float4*)&sK[r * 132 + cc] = f4_tf32(v);
            }
            __syncthreads();
            if ((w >> 1) == c) {
                const int lr = ((w & 1) << 4) + a_row;
#pragma unroll
                for (int kp = 0; kp < 8; kp++) {
                    ldsm4(&qf[kp][0], &sK[lr * 132 + (kp << 4) + a_csub]);
                    ldsm4(&qf[kp][4], &sK[lr * 132 + (kp << 4) + 8 + a_csub]);
                }
            }
            __syncthreads();
        }
    }

    float oacc[16][4];
#pragma unroll
    for (int i = 0; i < 16; i++)
#pragma unroll
        for (int j = 0; j < 4; j++) oacc[i][j] = 0.f;
    float m0 = -1e30f, m1 = -1e30f, l0 = 0.f, l1 = 0.f;

    const float scale = 0.08838834764831845f;
    const int row0 = qt + (w << 4) + grp;
    const int row1 = row0 + 8;
    const int wmax = qt + (w << 4) + 15;
    const int ntile = (qt >> 5) + 4;
    float* sPw = sP + w * 576;

    for (int st = 0; st < ntile; st++) {
        const int s0 = st << 5;
        __syncthreads();
        // Stage K [32][128] and VT [128][32]
        {
            const float* Kb = Kc + ((size_t)(b * Tt + s0) * NK + kh) * HD;
            const float* Vb = VT + ((size_t)(b * NK + kh) * HD) * Tt + s0;
#pragma unroll
            for (int u = 0; u < 4; u++) {
                int idx = tid + (u << 8);
                int r = idx >> 5, c = (idx & 31) << 2;
                float4 vk = *(const float4*)(Kb + (size_t)r * (NK * HD) + c);
                *(float4*)&sK[r * 132 + c] = f4_tf32(vk);
                int h = idx >> 3, cv = (idx & 7) << 2;
                float4 vv = *(const float4*)(Vb + (size_t)h * Tt + cv);
                *(float4*)&sVT[h * 36 + cv] = f4_tf32(vv);
            }
        }
        __syncthreads();

        if (s0 > wmax) continue;   // this warp's rows all precede the tile

        // S = Q @ K^T : warp m16 x n32, k=128
        float sacc[4][4];
#pragma unroll
        for (int i = 0; i < 4; i++)
#pragma unroll
            for (int j = 0; j < 4; j++) sacc[i][j] = 0.f;
#pragma unroll
        for (int kp = 0; kp < 8; kp++) {
#pragma unroll
            for (int nt = 0; nt < 4; nt++) {
                uint32_t bf[4];
                ldsm4(bf, &sK[((nt << 3) + b_row) * 132 + (kp << 4) + b_col]);
                mma_tf32(sacc[nt], qf[kp][0], qf[kp][1], qf[kp][2], qf[kp][3], bf[0], bf[1]);
                mma_tf32(sacc[nt], qf[kp][4], qf[kp][5], qf[kp][6], qf[kp][7], bf[2], bf[3]);
            }
        }

        // Mask + online softmax
        float mx0 = -1e30f, mx1 = -1e30f;
#pragma unroll
        for (int nt = 0; nt < 4; nt++) {
            int colb = s0 + (nt << 3) + (qd << 1);
            float v0 = sacc[nt][0] * scale;
            float v1 = sacc[nt][1] * scale;
            float v2 = sacc[nt][2] * scale;
            float v3 = sacc[nt][3] * scale;
            if (colb > row0)     v0 = -1e30f;
            if (colb + 1 > row0) v1 = -1e30f;
            if (colb > row1)     v2 = -1e30f;
            if (colb + 1 > row1) v3 = -1e30f;
            sacc[nt][0] = v0; sacc[nt][1] = v1; sacc[nt][2] = v2; sacc[nt][3] = v3;
            mx0 = fmaxf(mx0, fmaxf(v0, v1));
            mx1 = fmaxf(mx1, fmaxf(v2, v3));
        }
        mx0 = fmaxf(mx0, __shfl_xor_sync(0xffffffffu, mx0, 1));
        mx0 = fmaxf(mx0, __shfl_xor_sync(0xffffffffu, mx0, 2));
        mx1 = fmaxf(mx1, __shfl_xor_sync(0xffffffffu, mx1, 1));
        mx1 = fmaxf(mx1, __shfl_xor_sync(0xffffffffu, mx1, 2));
        float mn0 = fmaxf(m0, mx0), mn1 = fmaxf(m1, mx1);
        float a0 = __expf(m0 - mn0), a1 = __expf(m1 - mn1);
        m0 = mn0; m1 = mn1;
        float ps0 = 0.f, ps1 = 0.f;
#pragma unroll
        for (int nt = 0; nt < 4; nt++) {
            float p0 = __expf(sacc[nt][0] - m0);
            float p1 = __expf(sacc[nt][1] - m0);
            float p2 = __expf(sacc[nt][2] - m1);
            float p3 = __expf(sacc[nt][3] - m1);
            ps0 += p0 + p1; ps1 += p2 + p3;
            int col = (nt << 3) + (qd << 1);
            *(float2*)&sPw[grp * 36 + col] = make_float2(to_tf32(p0), to_tf32(p1));
            *(float2*)&sPw[(grp + 8) * 36 + col] = make_float2(to_tf32(p2), to_tf32(p3));
        }
        ps0 += __shfl_xor_sync(0xffffffffu, ps0, 1);
        ps0 += __shfl_xor_sync(0xffffffffu, ps0, 2);
        ps1 += __shfl_xor_sync(0xffffffffu, ps1, 1);
        ps1 += __shfl_xor_sync(0xffffffffu, ps1, 2);
        l0 = l0 * a0 + ps0;
        l1 = l1 * a1 + ps1;
#pragma unroll
        for (int nt = 0; nt < 16; nt++) {
            oacc[nt][0] *= a0; oacc[nt][1] *= a0;
            oacc[nt][2] *= a1; oacc[nt][3] *= a1;
        }
        __syncwarp();

        // O += P @ V : warp m16 x n128, k=32
#pragma unroll
        for (int kp = 0; kp < 2; kp++) {
            uint32_t af0[4], af1[4];
            ldsm4(af0, &sPw[a_row * 36 + (kp << 4) + a_csub]);
            ldsm4(af1, &sPw[a_row * 36 + (kp << 4) + 8 + a_csub]);
#pragma unroll
            for (int nt = 0; nt < 16; nt++) {
                uint32_t bf[4];
                ldsm4(bf, &sVT[((nt << 3) + b_row) * 36 + (kp << 4) + b_col]);
                mma_tf32(oacc[nt], af0[0], af0[1], af0[2], af0[3], bf[0], bf[1]);
                mma_tf32(oacc[nt], af1[0], af1[1], af1[2], af1[3], bf[2], bf[3]);
            }
        }
    }

    const float i0 = 1.0f / l0, i1 = 1.0f / l1;
    float* Ob0 = O + ((size_t)(b * Tt + row0) * NQ + n) * HD;
    float* Ob1 = O + ((size_t)(b * Tt + row1) * NQ + n) * HD;
#pragma unroll
    for (int nt = 0; nt < 16; nt++) {
        int col = (nt << 3) + (qd << 1);
        *(float2*)(Ob0 + col) = make_float2(oacc[nt][0] * i0, oacc[nt][1] * i0);
        *(float2*)(Ob1 + col) = make_float2(oacc[nt][2] * i1, oacc[nt][3] * i1);
    }
}

// ---------------------------------------------------------------------------
// Launch
// ---------------------------------------------------------------------------
extern "C" void kernel_launch(void* const* d_in, const int* in_sizes, int n_in,
                              void* d_out, int out_size) {
    (void)in_sizes; (void)n_in; (void)out_size;
    const float* x   = (const float*)d_in[0];
    const float* qw  = (const float*)d_in[1];
    const float* kw  = (const float*)d_in[2];
    const float* vw  = (const float*)d_in[3];
    const float* ow  = (const float*)d_in[4];
    const float* qnw = (const float*)d_in[5];
    const float* knw = (const float*)d_in[6];
    float* out = (float*)d_out;

    float *gq, *gk, *gvt, *go, *wtq, *wtk, *wtv, *wto;
    cudaGetSymbolAddress((void**)&gq, g_q);
    cudaGetSymbolAddress((void**)&gk, g_k);
    cudaGetSymbolAddress((void**)&gvt, g_vt);
    cudaGetSymbolAddress((void**)&go, g_o);
    cudaGetSymbolAddress((void**)&wtq, g_wtq);
    cudaGetSymbolAddress((void**)&wtk, g_wtk);
    cudaGetSymbolAddress((void**)&wtv, g_wtv);
    cudaGetSymbolAddress((void**)&wto, g_wto);

    const int M = MROWS;     // 4096
    const int NH = NQ * HD;  // 2048
    const int KHH = NK * HD; // 1024

    rope_table<<<(Tt * 64 + 255) / 256, 256>>>();

    transpose_k<<<dim3(NH / 32, Dd / 32), 256>>>(qw, wtq, Dd, NH);
    transpose_k<<<dim3(KHH / 32, Dd / 32), 256>>>(kw, wtk, Dd, KHH);
    transpose_k<<<dim3(KHH / 32, Dd / 32), 256>>>(vw, wtv, Dd, KHH);
    transpose_k<<<dim3(Dd / 32, NH / 32), 256>>>(ow, wto, NH, Dd);

    gemm_v3<<<dim3(NH / 128, M / 128), 256>>>(x, wtq, gq, M, NH, Dd, 0);
    gemm_v3<<<dim3(KHH / 128, M / 128), 256>>>(x, wtk, gk, M, KHH, Dd, 0);
    gemm_v3<<<dim3(KHH / 128, M / 128), 256>>>(x, wtv, gvt, M, KHH, Dd, 1);

    rms_rope<<<M * NQ, 128>>>(gq, qnw, NQ);
    rms_rope<<<M * NK, 128>>>(gk, knw, NK);

    size_t smem = (size_t)13440 * sizeof(float); // 53760 B
    cudaFuncSetAttribute(flash_v4, cudaFuncAttributeMaxDynamicSharedMemorySize, (int)smem);
    flash_v4<<<dim3(Tt / 128, NQ, Bb), 256, smem>>>(gq, gk, gvt, go);

    gemm_v3<<<dim3(Dd / 128, M / 128), 256>>>(go, wto, out, M, Dd, NH, 0);
}

// round 9
// speedup vs baseline: 4.0952x; 1.5729x over previous
#include <cuda_runtime.h>
#include <cuda_fp16.h>
#include <math.h>
#include <stdint.h>

// Problem constants (fixed by setup_inputs)
#define Bb 2
#define Tt 2048
#define Dd 2048
#define NQ 16
#define NK 8
#define HD 128
#define MROWS (Bb * Tt)

// Scratch (device globals: allocation-free rule)
__device__ float  g_q[(size_t)MROWS * NQ * HD];     // fp32 Q proj (pre-norm)
__device__ float  g_k[(size_t)MROWS * NK * HD];     // fp32 K proj (pre-norm)
__device__ __half g_qh[(size_t)MROWS * NQ * HD];    // half Q (post rms+rope)
__device__ __half g_kh[(size_t)MROWS * NK * HD];    // half K (post rms+rope)
__device__ __half g_vt[(size_t)Bb * NK * HD * Tt];  // half V^T [b][kh][h][t]
__device__ __half g_oh[(size_t)MROWS * NQ * HD];    // half attention output
__device__ __half g_wtq[2048 * 2048];               // q_w^T  [NH][D]
__device__ __half g_wtk[1024 * 2048];               // k_w^T
__device__ __half g_wtv[1024 * 2048];               // v_w^T
__device__ __half g_wto[2048 * 2048];               // o_w^T  [D][NH]
__device__ float  g_sin[Tt * 64];
__device__ float  g_cos[Tt * 64];

__device__ __forceinline__ uint32_t pack2(float a, float b) {
    __half2 h = __floats2half2_rn(a, b);
    return *(uint32_t*)&h;
}

__device__ __forceinline__ void mma_f16(float* d, const uint32_t* a,
                                        uint32_t b0, uint32_t b1) {
    asm volatile(
        "mma.sync.aligned.m16n8k16.row.col.f32.f16.f16.f32 "
        "{%0,%1,%2,%3}, {%4,%5,%6,%7}, {%8,%9}, {%0,%1,%2,%3};"
        : "+f"(d[0]), "+f"(d[1]), "+f"(d[2]), "+f"(d[3])
        : "r"(a[0]), "r"(a[1]), "r"(a[2]), "r"(a[3]), "r"(b0), "r"(b1));
}

__device__ __forceinline__ void ldsm4h(uint32_t* r, const __half* p) {
    uint32_t a = (uint32_t)__cvta_generic_to_shared(p);
    asm volatile("ldmatrix.sync.aligned.m8n8.x4.shared.b16 {%0,%1,%2,%3}, [%4];"
                 : "=r"(r[0]), "=r"(r[1]), "=r"(r[2]), "=r"(r[3]) : "r"(a));
}

// ---------------------------------------------------------------------------
// 32x32 tiled transpose + fp16 cvt: in[R][C] fp32 -> out[C][R] half
// ---------------------------------------------------------------------------
__global__ __launch_bounds__(256) void transpose_h(const float* __restrict__ in,
                                                   __half* __restrict__ out,
                                                   int R, int C) {
    __shared__ float t[32][33];
    const int bx = blockIdx.x << 5, by = blockIdx.y << 5;
    const int tx = threadIdx.x & 31, ty = threadIdx.x >> 5;
#pragma unroll
    for (int i = 0; i < 32; i += 8)
        t[ty + i][tx] = in[(size_t)(by + ty + i) * C + bx + tx];
    __syncthreads();
#pragma unroll
    for (int i = 0; i < 32; i += 8)
        out[(size_t)(bx + ty + i) * R + by + tx] = __float2half(t[tx][ty + i]);
}

// ---------------------------------------------------------------------------
// fp16 GEMM: C[M,N] = A[M,K] @ BT[N,K]^T, fp32 accumulate.
// Block 128x128x32, 256 threads, 8 warps (2m x 4n), warp tile 64x32.
// ---------------------------------------------------------------------------
template <int AHALF, int VT>
__global__ __launch_bounds__(256) void gemm_h(const void* __restrict__ Av,
                                              const __half* __restrict__ BT,
                                              void* __restrict__ Cv,
                                              int M, int N, int K) {
    __shared__ __half sA[2][128 * 40];
    __shared__ __half sB[2][128 * 40];
    const int tid = threadIdx.x;
    const int bm = blockIdx.y << 7, bn = blockIdx.x << 7;
    const int warp = tid >> 5, lane = tid & 31;
    const int wm = (warp >> 2) << 6, wn = (warp & 3) << 5;
    const int grp = lane >> 2, qd = lane & 3;

    const int rs = tid >> 1;        // 0..127
    const int cb = (tid & 1) << 4;  // 0 or 16 halves

    const int a_row = (lane & 7) + ((lane >> 3) & 1) * 8;
    const int a_col = ((lane >> 4) & 1) * 8;
    const int b_row = (lane & 7) + ((lane >> 4) & 1) * 8;
    const int b_col = ((lane >> 3) & 1) * 8;

    float acc[4][4][4];
#pragma unroll
    for (int i = 0; i < 4; i++)
#pragma unroll
        for (int j = 0; j < 4; j++)
#pragma unroll
            for (int r = 0; r < 4; r++) acc[i][j][r] = 0.f;

    float4 pa[4];
    uint4 pah[2], pb[2];

    const float* Af = (const float*)Av;
    const __half* Ah = (const __half*)Av;

    // prefetch tile 0
    {
        if (!AHALF) {
            const float* p = Af + (size_t)(bm + rs) * K + cb;
            pa[0] = *(const float4*)p; pa[1] = *(const float4*)(p + 4);
            pa[2] = *(const float4*)(p + 8); pa[3] = *(const float4*)(p + 12);
        } else {
            const __half* p = Ah + (size_t)(bm + rs) * K + cb;
            pah[0] = *(const uint4*)p; pah[1] = *(const uint4*)(p + 8);
        }
        const __half* q = BT + (size_t)(bn + rs) * K + cb;
        pb[0] = *(const uint4*)q; pb[1] = *(const uint4*)(q + 8);
    }

    const int nkt = K >> 5;
    // store tile 0
    {
        __half* da = &sA[0][rs * 40 + cb];
        if (!AHALF) {
            uint4 w0 = make_uint4(pack2(pa[0].x, pa[0].y), pack2(pa[0].z, pa[0].w),
                                  pack2(pa[1].x, pa[1].y), pack2(pa[1].z, pa[1].w));
            uint4 w1 = make_uint4(pack2(pa[2].x, pa[2].y), pack2(pa[2].z, pa[2].w),
                                  pack2(pa[3].x, pa[3].y), pack2(pa[3].z, pa[3].w));
            *(uint4*)da = w0; *(uint4*)(da + 8) = w1;
        } else {
            *(uint4*)da = pah[0]; *(uint4*)(da + 8) = pah[1];
        }
        __half* db = &sB[0][rs * 40 + cb];
        *(uint4*)db = pb[0]; *(uint4*)(db + 8) = pb[1];
    }
    __syncthreads();

    for (int kt = 0; kt < nkt; kt++) {
        const int buf = kt & 1;
        if (kt + 1 < nkt) {
            const int k0 = (kt + 1) << 5;
            if (!AHALF) {
                const float* p = Af + (size_t)(bm + rs) * K + k0 + cb;
                pa[0] = *(const float4*)p; pa[1] = *(const float4*)(p + 4);
                pa[2] = *(const float4*)(p + 8); pa[3] = *(const float4*)(p + 12);
            } else {
                const __half* p = Ah + (size_t)(bm + rs) * K + k0 + cb;
                pah[0] = *(const uint4*)p; pah[1] = *(const uint4*)(p + 8);
            }
            const __half* q = BT + (size_t)(bn + rs) * K + k0 + cb;
            pb[0] = *(const uint4*)q; pb[1] = *(const uint4*)(q + 8);
        }
#pragma unroll
        for (int ks = 0; ks < 2; ks++) {
            uint32_t af[4][4], bf[2][4];
#pragma unroll
            for (int mt = 0; mt < 4; mt++)
                ldsm4h(af[mt], &sA[buf][(wm + mt * 16 + a_row) * 40 + ks * 16 + a_col]);
#pragma unroll
            for (int np = 0; np < 2; np++)
                ldsm4h(bf[np], &sB[buf][(wn + np * 16 + b_row) * 40 + ks * 16 + b_col]);
            // matrix order with this address map: {n0-7/k0-7, n0-7/k8-15,
            //  n8-15/k0-7, n8-15/k8-15} -> n-block j uses (bf[2j], bf[2j+1])
#pragma unroll
            for (int mt = 0; mt < 4; mt++)
#pragma unroll
                for (int nt = 0; nt < 4; nt++)
                    mma_f16(acc[mt][nt], af[mt],
                            bf[nt >> 1][(nt & 1) * 2], bf[nt >> 1][(nt & 1) * 2 + 1]);
        }
        if (kt + 1 < nkt) {
            const int nb = buf ^ 1;
            __half* da = &sA[nb][rs * 40 + cb];
            if (!AHALF) {
                uint4 w0 = make_uint4(pack2(pa[0].x, pa[0].y), pack2(pa[0].z, pa[0].w),
                                      pack2(pa[1].x, pa[1].y), pack2(pa[1].z, pa[1].w));
                uint4 w1 = make_uint4(pack2(pa[2].x, pa[2].y), pack2(pa[2].z, pa[2].w),
                                      pack2(pa[3].x, pa[3].y), pack2(pa[3].z, pa[3].w));
                *(uint4*)da = w0; *(uint4*)(da + 8) = w1;
            } else {
                *(uint4*)da = pah[0]; *(uint4*)(da + 8) = pah[1];
            }
            __half* db = &sB[nb][rs * 40 + cb];
            *(uint4*)db = pb[0]; *(uint4*)(db + 8) = pb[1];
        }
        __syncthreads();
    }

    if (!VT) {
        float* C = (float*)Cv;
#pragma unroll
        for (int mt = 0; mt < 4; mt++)
#pragma unroll
            for (int nt = 0; nt < 4; nt++) {
                int row = bm + wm + (mt << 4) + grp;
                int col = bn + wn + (nt << 3) + (qd << 1);
                *(float2*)(C + (size_t)row * N + col) =
                    make_float2(acc[mt][nt][0], acc[mt][nt][1]);
                *(float2*)(C + (size_t)(row + 8) * N + col) =
                    make_float2(acc[mt][nt][2], acc[mt][nt][3]);
            }
    } else {
        __half* C = (__half*)Cv;
#pragma unroll
        for (int mt = 0; mt < 4; mt++)
#pragma unroll
            for (int nt = 0; nt < 4; nt++) {
                int row = bm + wm + (mt << 4) + grp;
                int col = bn + wn + (nt << 3) + (qd << 1);
                int b = row >> 11, t = row & 2047;
                size_t base0 = ((size_t)b * NK * HD + col) * Tt + t;
                size_t base1 = ((size_t)b * NK * HD + col + 1) * Tt + t;
                C[base0] = __float2half(acc[mt][nt][0]);
                C[base1] = __float2half(acc[mt][nt][1]);
                C[base0 + 8] = __float2half(acc[mt][nt][2]);
                C[base1 + 8] = __float2half(acc[mt][nt][3]);
            }
    }
}

// ---------------------------------------------------------------------------
// RoPE table
// ---------------------------------------------------------------------------
__global__ __launch_bounds__(256) void rope_table() {
    int idx = blockIdx.x * 256 + threadIdx.x;
    if (idx >= Tt * 64) return;
    int t = idx >> 6, i = idx & 63;
    double ang = (double)t * exp(-0.21586735246819178 * (double)i);
    double s, c;
    sincos(ang, &s, &c);
    g_sin[idx] = (float)s;
    g_cos[idx] = (float)c;
}

// ---------------------------------------------------------------------------
// Fused RMSNorm + RoPE: fp32 in, half out
// ---------------------------------------------------------------------------
__global__ __launch_bounds__(128) void rms_rope_h(const float* __restrict__ in,
                                                  __half* __restrict__ outb,
                                                  const float* __restrict__ w,
                                                  int heads) {
    const int idx = blockIdx.x;
    const int t = (idx / heads) % Tt;
    const float* p = in + (size_t)idx * HD;
    const int h = threadIdx.x;

    float x = p[h];
    float ss = x * x;
#pragma unroll
    for (int off = 16; off; off >>= 1) ss += __shfl_xor_sync(0xffffffffu, ss, off);
    __shared__ float red[4];
    __shared__ float sy[HD];
    if ((h & 31) == 0) red[h >> 5] = ss;
    __syncthreads();
    float tot = red[0] + red[1] + red[2] + red[3];
    float rinv = rsqrtf(tot * (1.0f / (float)HD) + 1e-6f);
    float y = w[h] * x * rinv;
    sy[h] = y;
    __syncthreads();

    int i = h & 63;
    float s = g_sin[t * 64 + i];
    float c = g_cos[t * 64 + i];
    float out;
    if (h < 64) out = y * c - sy[h + 64] * s;
    else        out = y * c + sy[h - 64] * s;
    outb[(size_t)idx * HD + h] = __float2half(out);
}

// ---------------------------------------------------------------------------
// Flash attention fp16 mma. 256 threads (8 warps), q-tile 128 (warp = 16 rows,
// Q frags in regs), s-tile 32, fp32 softmax/accum.
//   sK  [32][136] halves (also Q staging)   sVT [128][40]   sP 8x[16][40]
// ---------------------------------------------------------------------------
__global__ __launch_bounds__(256) void flash_h(const __half* __restrict__ Q,
                                               const __half* __restrict__ Kc,
                                               const __half* __restrict__ VT,
                                               __half* __restrict__ O) {
    __shared__ __half sK[32 * 136];
    __shared__ __half sVT[128 * 40];
    __shared__ __half sP[8 * 16 * 40];

    const int tid = threadIdx.x;
    const int w = tid >> 5, lane = tid & 31;
    const int grp = lane >> 2, qd = lane & 3;
    const int b = blockIdx.z, n = blockIdx.y;
    const int qt = blockIdx.x << 7;
    const int kh = n >> 1;

    const int a_row = (lane & 7) + ((lane >> 3) & 1) * 8;
    const int a_col = ((lane >> 4) & 1) * 8;
    const int b_row = (lane & 7) + ((lane >> 4) & 1) * 8;
    const int b_col = ((lane >> 3) & 1) * 8;

    // Load Q fragments into registers (staged through sK, 32-row chunks)
    uint32_t qf[8][4];
    {
        const __half* Qb = Q + ((size_t)(b * Tt + qt) * NQ + n) * HD;
#pragma unroll
        for (int c = 0; c < 4; c++) {
#pragma unroll
            for (int u = 0; u < 2; u++) {
                int idx = tid + (u << 8);
                int r = idx >> 4, c8 = (idx & 15) << 3;
                *(uint4*)&sK[r * 136 + c8] =
                    *(const uint4*)(Qb + (size_t)(c * 32 + r) * (NQ * HD) + c8);
            }
            __syncthreads();
            if ((w >> 1) == c) {
                const int lr = ((w & 1) << 4) + a_row;
#pragma unroll
                for (int kp = 0; kp < 8; kp++)
                    ldsm4h(qf[kp], &sK[lr * 136 + (kp << 4) + a_col]);
            }
            __syncthreads();
        }
    }

    float oacc[16][4];
#pragma unroll
    for (int i = 0; i < 16; i++)
#pragma unroll
        for (int j = 0; j < 4; j++) oacc[i][j] = 0.f;
    float m0 = -1e30f, m1 = -1e30f, l0 = 0.f, l1 = 0.f;

    const float scale = 0.08838834764831845f;
    const int row0 = qt + (w << 4) + grp;
    const int row1 = row0 + 8;
    const int wmax = qt + (w << 4) + 15;
    const int ntile = (qt >> 5) + 4;
    __half* sPw = sP + w * 640;

    for (int st = 0; st < ntile; st++) {
        const int s0 = st << 5;
        __syncthreads();
        {
            const __half* Kb = Kc + ((size_t)(b * Tt + s0) * NK + kh) * HD;
            const __half* Vb = VT + ((size_t)(b * NK + kh) * HD) * Tt + s0;
#pragma unroll
            for (int u = 0; u < 2; u++) {
                int idx = tid + (u << 8);
                int r = idx >> 4, c8 = (idx & 15) << 3;
                *(uint4*)&sK[r * 136 + c8] =
                    *(const uint4*)(Kb + (size_t)r * (NK * HD) + c8);
                int rv = idx >> 2, cv = (idx & 3) << 3;
                *(uint4*)&sVT[rv * 40 + cv] = *(const uint4*)(Vb + (size_t)rv * Tt + cv);
            }
        }
        __syncthreads();

        if (s0 > wmax) continue;

        // S = Q @ K^T : warp m16 x n32, k=128
        float sacc[4][4];
#pragma unroll
        for (int i = 0; i < 4; i++)
#pragma unroll
            for (int j = 0; j < 4; j++) sacc[i][j] = 0.f;
#pragma unroll
        for (int kp = 0; kp < 8; kp++) {
            uint32_t bf[2][4];
#pragma unroll
            for (int np = 0; np < 2; np++)
                ldsm4h(bf[np], &sK[(np * 16 + b_row) * 136 + (kp << 4) + b_col]);
#pragma unroll
            for (int nt = 0; nt < 4; nt++)
                mma_f16(sacc[nt], qf[kp],
                        bf[nt >> 1][(nt & 1) * 2], bf[nt >> 1][(nt & 1) * 2 + 1]);
        }

        // Mask + online softmax
        float mx0 = -1e30f, mx1 = -1e30f;
#pragma unroll
        for (int nt = 0; nt < 4; nt++) {
            int colb = s0 + (nt << 3) + (qd << 1);
            float v0 = sacc[nt][0] * scale;
            float v1 = sacc[nt][1] * scale;
            float v2 = sacc[nt][2] * scale;
            float v3 = sacc[nt][3] * scale;
            if (colb > row0)     v0 = -1e30f;
            if (colb + 1 > row0) v1 = -1e30f;
            if (colb > row1)     v2 = -1e30f;
            if (colb + 1 > row1) v3 = -1e30f;
            sacc[nt][0] = v0; sacc[nt][1] = v1; sacc[nt][2] = v2; sacc[nt][3] = v3;
            mx0 = fmaxf(mx0, fmaxf(v0, v1));
            mx1 = fmaxf(mx1, fmaxf(v2, v3));
        }
        mx0 = fmaxf(mx0, __shfl_xor_sync(0xffffffffu, mx0, 1));
        mx0 = fmaxf(mx0, __shfl_xor_sync(0xffffffffu, mx0, 2));
        mx1 = fmaxf(mx1, __shfl_xor_sync(0xffffffffu, mx1, 1));
        mx1 = fmaxf(mx1, __shfl_xor_sync(0xffffffffu, mx1, 2));
        float mn0 = fmaxf(m0, mx0), mn1 = fmaxf(m1, mx1);
        float a0 = __expf(m0 - mn0), a1 = __expf(m1 - mn1);
        m0 = mn0; m1 = mn1;
        float ps0 = 0.f, ps1 = 0.f;
#pragma unroll
        for (int nt = 0; nt < 4; nt++) {
            float p0 = __expf(sacc[nt][0] - m0);
            float p1 = __expf(sacc[nt][1] - m0);
            float p2 = __expf(sacc[nt][2] - m1);
            float p3 = __expf(sacc[nt][3] - m1);
            ps0 += p0 + p1; ps1 += p2 + p3;
            int col = (nt << 3) + (qd << 1);
            *(uint32_t*)&sPw[grp * 40 + col] = pack2(p0, p1);
            *(uint32_t*)&sPw[(grp + 8) * 40 + col] = pack2(p2, p3);
        }
        ps0 += __shfl_xor_sync(0xffffffffu, ps0, 1);
        ps0 += __shfl_xor_sync(0xffffffffu, ps0, 2);
        ps1 += __shfl_xor_sync(0xffffffffu, ps1, 1);
        ps1 += __shfl_xor_sync(0xffffffffu, ps1, 2);
        l0 = l0 * a0 + ps0;
        l1 = l1 * a1 + ps1;
#pragma unroll
        for (int nt = 0; nt < 16; nt++) {
            oacc[nt][0] *= a0; oacc[nt][1] *= a0;
            oacc[nt][2] *= a1; oacc[nt][3] *= a1;
        }
        __syncwarp();

        // O += P @ V : warp m16 x n128, k=32
#pragma unroll
        for (int kp = 0; kp < 2; kp++) {
            uint32_t af[4];
            ldsm4h(af, &sPw[a_row * 40 + (kp << 4) + a_col]);
#pragma unroll
            for (int np = 0; np < 8; np++) {
                uint32_t bf[4];
                ldsm4h(bf, &sVT[(np * 16 + b_row) * 40 + (kp << 4) + b_col]);
                mma_f16(oacc[np * 2], af, bf[0], bf[1]);
                mma_f16(oacc[np * 2 + 1], af, bf[2], bf[3]);
            }
        }
    }

    const float i0 = 1.0f / l0, i1 = 1.0f / l1;
    __half* Ob0 = O + ((size_t)(b * Tt + row0) * NQ + n) * HD;
    __half* Ob1 = O + ((size_t)(b * Tt + row1) * NQ + n) * HD;
#pragma unroll
    for (int nt = 0; nt < 16; nt++) {
        int col = (nt << 3) + (qd << 1);
        *(uint32_t*)(Ob0 + col) = pack2(oacc[nt][0] * i0, oacc[nt][1] * i0);
        *(uint32_t*)(Ob1 + col) = pack2(oacc[nt][2] * i1, oacc[nt][3] * i1);
    }
}

// ---------------------------------------------------------------------------
// Launch (ordered so launch #6 = Q-projection GEMM for ncu -s 5 -c 1)
// ---------------------------------------------------------------------------
extern "C" void kernel_launch(void* const* d_in, const int* in_sizes, int n_in,
                              void* d_out, int out_size) {
    (void)in_sizes; (void)n_in; (void)out_size;
    const float* x   = (const float*)d_in[0];
    const float* qw  = (const float*)d_in[1];
    const float* kw  = (const float*)d_in[2];
    const float* vw  = (const float*)d_in[3];
    const float* ow  = (const float*)d_in[4];
    const float* qnw = (const float*)d_in[5];
    const float* knw = (const float*)d_in[6];
    float* out = (float*)d_out;

    float *gq, *gk;
    __half *gqh, *gkh, *gvt, *goh, *wtq, *wtk, *wtv, *wto;
    cudaGetSymbolAddress((void**)&gq, g_q);
    cudaGetSymbolAddress((void**)&gk, g_k);
    cudaGetSymbolAddress((void**)&gqh, g_qh);
    cudaGetSymbolAddress((void**)&gkh, g_kh);
    cudaGetSymbolAddress((void**)&gvt, g_vt);
    cudaGetSymbolAddress((void**)&goh, g_oh);
    cudaGetSymbolAddress((void**)&wtq, g_wtq);
    cudaGetSymbolAddress((void**)&wtk, g_wtk);
    cudaGetSymbolAddress((void**)&wtv, g_wtv);
    cudaGetSymbolAddress((void**)&wto, g_wto);

    const int M = MROWS;     // 4096
    const int NH = NQ * HD;  // 2048
    const int KHH = NK * HD; // 1024

    // launches 1-4: weight transposes (fp32 -> half, transposed)
    transpose_h<<<dim3(NH / 32, Dd / 32), 256>>>(qw, wtq, Dd, NH);
    transpose_h<<<dim3(KHH / 32, Dd / 32), 256>>>(kw, wtk, Dd, KHH);
    transpose_h<<<dim3(KHH / 32, Dd / 32), 256>>>(vw, wtv, Dd, KHH);
    transpose_h<<<dim3(Dd / 32, NH / 32), 256>>>(ow, wto, NH, Dd);
    // launch 5: rope table
    rope_table<<<(Tt * 64 + 255) / 256, 256>>>();

    // launch 6: Q projection (profiled by ncu)
    gemm_h<0, 0><<<dim3(NH / 128, M / 128), 256>>>(x, wtq, gq, M, NH, Dd);
    gemm_h<0, 0><<<dim3(KHH / 128, M / 128), 256>>>(x, wtk, gk, M, KHH, Dd);
    gemm_h<0, 1><<<dim3(KHH / 128, M / 128), 256>>>(x, wtv, gvt, M, KHH, Dd);

    rms_rope_h<<<M * NQ, 128>>>(gq, gqh, qnw, NQ);
    rms_rope_h<<<M * NK, 128>>>(gk, gkh, knw, NK);

    flash_h<<<dim3(Tt / 128, NQ, Bb), 256>>>(gqh, gkh, gvt, goh);

    gemm_h<1, 0><<<dim3(Dd / 128, M / 128), 256>>>(goh, wto, out, M, Dd, NH);
}

// round 11
// speedup vs baseline: 4.9558x; 1.2102x over previous
#include <cuda_runtime.h>
#include <cuda_fp16.h>
#include <math.h>
#include <stdint.h>

#define Bb 2
#define Tt 2048
#define Dd 2048
#define NQ 16
#define NK 8
#define HD 128
#define MROWS (Bb * Tt)

// Scratch (device globals: allocation-free rule)
__device__ float  g_q[(size_t)MROWS * NQ * HD];     // fp32 Q proj (pre-norm)
__device__ float  g_k[(size_t)MROWS * NK * HD];     // fp32 K proj (pre-norm)
__device__ __half g_xh[(size_t)MROWS * Dd];         // half x
__device__ __half g_qh[(size_t)MROWS * NQ * HD];    // half Q (post rms+rope)
__device__ __half g_kh[(size_t)MROWS * NK * HD];    // half K (post rms+rope)
__device__ __half g_vt[(size_t)Bb * NK * HD * Tt];  // half V^T [b][kh][h][t]
__device__ __half g_oh[(size_t)MROWS * NQ * HD];    // half attention output
__device__ __half g_wtq[2048 * 2048];
__device__ __half g_wtk[1024 * 2048];
__device__ __half g_wtv[1024 * 2048];
__device__ __half g_wto[2048 * 2048];
__device__ float  g_sin[Tt * 64];
__device__ float  g_cos[Tt * 64];

__device__ __forceinline__ uint32_t pack2(float a, float b) {
    __half2 h = __floats2half2_rn(a, b);
    return *(uint32_t*)&h;
}

__device__ __forceinline__ void mma_f16(float* d, const uint32_t* a,
                                        uint32_t b0, uint32_t b1) {
    asm volatile(
        "mma.sync.aligned.m16n8k16.row.col.f32.f16.f16.f32 "
        "{%0,%1,%2,%3}, {%4,%5,%6,%7}, {%8,%9}, {%0,%1,%2,%3};"
        : "+f"(d[0]), "+f"(d[1]), "+f"(d[2]), "+f"(d[3])
        : "r"(a[0]), "r"(a[1]), "r"(a[2]), "r"(a[3]), "r"(b0), "r"(b1));
}

__device__ __forceinline__ void ldsm4h(uint32_t* r, const __half* p) {
    uint32_t a = (uint32_t)__cvta_generic_to_shared(p);
    asm volatile("ldmatrix.sync.aligned.m8n8.x4.shared.b16 {%0,%1,%2,%3}, [%4];"
                 : "=r"(r[0]), "=r"(r[1]), "=r"(r[2]), "=r"(r[3]) : "r"(a));
}

__device__ __forceinline__ void cpa16(void* dst, const void* src) {
    uint32_t d = (uint32_t)__cvta_generic_to_shared(dst);
    asm volatile("cp.async.cg.shared.global [%0], [%1], 16;" :: "r"(d), "l"(src));
}
#define CP_COMMIT asm volatile("cp.async.commit_group;")
#define CP_WAIT(n) asm volatile("cp.async.wait_group %0;" :: "n"(n))

// ---------------------------------------------------------------------------
// fp32 -> fp16 bulk convert (8 elems/thread)
// ---------------------------------------------------------------------------
__global__ __launch_bounds__(256) void cvt_half(const float* __restrict__ in,
                                                __half* __restrict__ out) {
    size_t i = ((size_t)blockIdx.x * 256 + threadIdx.x) * 8;
    float4 a = *(const float4*)(in + i);
    float4 b = *(const float4*)(in + i + 4);
    uint4 w = make_uint4(pack2(a.x, a.y), pack2(a.z, a.w),
                         pack2(b.x, b.y), pack2(b.z, b.w));
    *(uint4*)(out + i) = w;
}

// ---------------------------------------------------------------------------
// 32x32 tiled transpose + fp16 cvt: in[R][C] fp32 -> out[C][R] half
// ---------------------------------------------------------------------------
__global__ __launch_bounds__(256) void transpose_h(const float* __restrict__ in,
                                                   __half* __restrict__ out,
                                                   int R, int C) {
    __shared__ float t[32][33];
    const int bx = blockIdx.x << 5, by = blockIdx.y << 5;
    const int tx = threadIdx.x & 31, ty = threadIdx.x >> 5;
#pragma unroll
    for (int i = 0; i < 32; i += 8)
        t[ty + i][tx] = in[(size_t)(by + ty + i) * C + bx + tx];
    __syncthreads();
#pragma unroll
    for (int i = 0; i < 32; i += 8)
        out[(size_t)(bx + ty + i) * R + by + tx] = __float2half(t[tx][ty + i]);
}

// ---------------------------------------------------------------------------
// fp16 GEMM with cp.async 2-stage pipeline. C[M,N] = A[M,K] @ BT[N,K]^T.
// Block 128x128x32, 256 threads, 8 warps (2m x 4n), warp tile 64x32.
// Each thread stages 2x16B per operand per tile (full 8KB coverage).
// ---------------------------------------------------------------------------
template <int VT>
__global__ __launch_bounds__(256) void gemm_h2(const __half* __restrict__ A,
                                               const __half* __restrict__ BT,
                                               void* __restrict__ Cv,
                                               int M, int N, int K) {
    __shared__ __half sA[2][128 * 40];
    __shared__ __half sB[2][128 * 40];
    const int tid = threadIdx.x;
    const int bm = blockIdx.y << 7, bn = blockIdx.x << 7;
    const int warp = tid >> 5, lane = tid & 31;
    const int wm = (warp >> 2) << 6, wn = (warp & 3) << 5;
    const int grp = lane >> 2, qd = lane & 3;

    const int rs = tid >> 1;        // 0..127
    const int cb = (tid & 1) << 4;  // 0 or 16 halves

    const int a_row = (lane & 7) + ((lane >> 3) & 1) * 8;
    const int a_col = ((lane >> 4) & 1) * 8;
    const int b_row = (lane & 7) + ((lane >> 4) & 1) * 8;
    const int b_col = ((lane >> 3) & 1) * 8;

    float acc[4][4][4];
#pragma unroll
    for (int i = 0; i < 4; i++)
#pragma unroll
        for (int j = 0; j < 4; j++)
#pragma unroll
            for (int r = 0; r < 4; r++) acc[i][j][r] = 0.f;

    const __half* Ap = A + (size_t)(bm + rs) * K + cb;
    const __half* Bp = BT + (size_t)(bn + rs) * K + cb;

    // prologue: stage tile 0 (16 halves = 2 x 16B per thread per operand)
    cpa16(&sA[0][rs * 40 + cb], Ap);
    cpa16(&sA[0][rs * 40 + cb + 8], Ap + 8);
    cpa16(&sB[0][rs * 40 + cb], Bp);
    cpa16(&sB[0][rs * 40 + cb + 8], Bp + 8);
    CP_COMMIT;

    const int nkt = K >> 5;
    for (int kt = 0; kt < nkt; kt++) {
        const int buf = kt & 1;
        if (kt + 1 < nkt) {
            const int k0 = (kt + 1) << 5;
            const int nb = buf ^ 1;
            cpa16(&sA[nb][rs * 40 + cb], Ap + k0);
            cpa16(&sA[nb][rs * 40 + cb + 8], Ap + k0 + 8);
            cpa16(&sB[nb][rs * 40 + cb], Bp + k0);
            cpa16(&sB[nb][rs * 40 + cb + 8], Bp + k0 + 8);
            CP_COMMIT;
            CP_WAIT(1);
        } else {
            CP_WAIT(0);
        }
        __syncthreads();
#pragma unroll
        for (int ks = 0; ks < 2; ks++) {
            uint32_t af[4][4], bf[2][4];
#pragma unroll
            for (int mt = 0; mt < 4; mt++)
                ldsm4h(af[mt], &sA[buf][(wm + mt * 16 + a_row) * 40 + ks * 16 + a_col]);
#pragma unroll
            for (int np = 0; np < 2; np++)
                ldsm4h(bf[np], &sB[buf][(wn + np * 16 + b_row) * 40 + ks * 16 + b_col]);
#pragma unroll
            for (int mt = 0; mt < 4; mt++)
#pragma unroll
                for (int nt = 0; nt < 4; nt++)
                    mma_f16(acc[mt][nt], af[mt],
                            bf[nt >> 1][(nt & 1) * 2], bf[nt >> 1][(nt & 1) * 2 + 1]);
        }
        __syncthreads();
    }

    if (!VT) {
        float* C = (float*)Cv;
#pragma unroll
        for (int mt = 0; mt < 4; mt++)
#pragma unroll
            for (int nt = 0; nt < 4; nt++) {
                int row = bm + wm + (mt << 4) + grp;
                int col = bn + wn + (nt << 3) + (qd << 1);
                *(float2*)(C + (size_t)row * N + col) =
                    make_float2(acc[mt][nt][0], acc[mt][nt][1]);
                *(float2*)(C + (size_t)(row + 8) * N + col) =
                    make_float2(acc[mt][nt][2], acc[mt][nt][3]);
            }
    } else {
        __half* C = (__half*)Cv;
#pragma unroll
        for (int mt = 0; mt < 4; mt++)
#pragma unroll
            for (int nt = 0; nt < 4; nt++) {
                int row = bm + wm + (mt << 4) + grp;
                int col = bn + wn + (nt << 3) + (qd << 1);
                int b = row >> 11, t = row & 2047;
                size_t base0 = ((size_t)b * NK * HD + col) * Tt + t;
                size_t base1 = ((size_t)b * NK * HD + col + 1) * Tt + t;
                C[base0] = __float2half(acc[mt][nt][0]);
                C[base1] = __float2half(acc[mt][nt][1]);
                C[base0 + 8] = __float2half(acc[mt][nt][2]);
                C[base1 + 8] = __float2half(acc[mt][nt][3]);
            }
    }
}

// ---------------------------------------------------------------------------
// RoPE table
// ---------------------------------------------------------------------------
__global__ __launch_bounds__(256) void rope_table() {
    int idx = blockIdx.x * 256 + threadIdx.x;
    if (idx >= Tt * 64) return;
    int t = idx >> 6, i = idx & 63;
    double ang = (double)t * exp(-0.21586735246819178 * (double)i);
    double s, c;
    sincos(ang, &s, &c);
    g_sin[idx] = (float)s;
    g_cos[idx] = (float)c;
}

// ---------------------------------------------------------------------------
// Fused RMSNorm + RoPE v2: 1 warp per (row, head), float4, no smem/syncs.
// ---------------------------------------------------------------------------
__global__ __launch_bounds__(256) void rms_rope_v2(const float* __restrict__ in,
                                                   __half* __restrict__ outb,
                                                   const float* __restrict__ w,
                                                   int heads) {
    const int gw = blockIdx.x * 8 + (threadIdx.x >> 5);
    const int lane = threadIdx.x & 31;
    const int t = (gw / heads) % Tt;

    float4 x = *(const float4*)(in + (size_t)gw * HD + lane * 4);
    float ss = x.x * x.x + x.y * x.y + x.z * x.z + x.w * x.w;
#pragma unroll
    for (int off = 16; off; off >>= 1) ss += __shfl_xor_sync(0xffffffffu, ss, off);
    float rinv = rsqrtf(ss * (1.0f / (float)HD) + 1e-6f);

    float4 wv = *(const float4*)(w + lane * 4);
    float y[4] = {wv.x * x.x * rinv, wv.y * x.y * rinv,
                  wv.z * x.z * rinv, wv.w * x.w * rinv};
    float yp[4];
#pragma unroll
    for (int j = 0; j < 4; j++) yp[j] = __shfl_xor_sync(0xffffffffu, y[j], 16);

    const int i0 = ((lane & 15) << 2);
    float o[4];
#pragma unroll
    for (int j = 0; j < 4; j++) {
        float s = g_sin[t * 64 + i0 + j];
        float c = g_cos[t * 64 + i0 + j];
        o[j] = (lane < 16) ? (y[j] * c - yp[j] * s) : (y[j] * c + yp[j] * s);
    }
    uint2 pk = make_uint2(pack2(o[0], o[1]), pack2(o[2], o[3]));
    *(uint2*)(outb + (size_t)gw * HD + lane * 4) = pk;
}

// ---------------------------------------------------------------------------
// Flash attention fp16, s-tile 64, cp.async double-buffered K/V.
// 256 threads (8 warps), q-tile 128 (warp = 16 rows, Q frags in regs).
// Dynamic smem: sK 2x[64][136], sVT 2x[128][72], sP 8x[16][72]  (90112 B)
// ---------------------------------------------------------------------------
__global__ __launch_bounds__(256) void flash_h2(const __half* __restrict__ Q,
                                                const __half* __restrict__ Kc,
                                                const __half* __restrict__ VT,
                                                __half* __restrict__ O) {
    extern __shared__ __half smh[];
    __half* sK = smh;                  // 2 * 8704
    __half* sVT = sK + 2 * 8704;       // 2 * 9216
    __half* sP = sVT + 2 * 9216;       // 8 * 1152

    const int tid = threadIdx.x;
    const int w = tid >> 5, lane = tid & 31;
    const int grp = lane >> 2, qd = lane & 3;
    const int b = blockIdx.z, n = blockIdx.y;
    const int qt = blockIdx.x << 7;
    const int kh = n >> 1;

    const int a_row = (lane & 7) + ((lane >> 3) & 1) * 8;
    const int a_col = ((lane >> 4) & 1) * 8;
    const int b_row = (lane & 7) + ((lane >> 4) & 1) * 8;
    const int b_col = ((lane >> 3) & 1) * 8;

    // Load Q fragments into registers (staged through sK, 64-row chunks)
    uint32_t qf[8][4];
    {
        const __half* Qb = Q + ((size_t)(b * Tt + qt) * NQ + n) * HD;
#pragma unroll
        for (int c = 0; c < 2; c++) {
            __half* sKc = sK + c * 8704;
#pragma unroll
            for (int u = 0; u < 4; u++) {
                int cc = tid + (u << 8);
                int r = cc >> 4, ch = (cc & 15) << 3;
                *(uint4*)&sKc[r * 136 + ch] =
                    *(const uint4*)(Qb + (size_t)(c * 64 + r) * (NQ * HD) + ch);
            }
            __syncthreads();
            if ((w >> 2) == c) {
                const int lr = ((w & 3) << 4) + a_row;
#pragma unroll
                for (int kp = 0; kp < 8; kp++)
                    ldsm4h(qf[kp], &sKc[lr * 136 + (kp << 4) + a_col]);
            }
            __syncthreads();
        }
    }

    float oacc[16][4];
#pragma unroll
    for (int i = 0; i < 16; i++)
#pragma unroll
        for (int j = 0; j < 4; j++) oacc[i][j] = 0.f;
    float m0 = -1e30f, m1 = -1e30f, l0 = 0.f, l1 = 0.f;

    const float scale = 0.08838834764831845f;
    const int row0 = qt + (w << 4) + grp;
    const int row1 = row0 + 8;
    const int wmax = qt + (w << 4) + 15;
    const int ntile = (qt >> 6) + 2;
    __half* sPw = sP + w * 1152;

    const __half* Kbase = Kc + ((size_t)b * Tt * NK + kh) * HD;
    const __half* Vbase = VT + ((size_t)(b * NK + kh) * HD) * Tt;

    // stage K/V tile st into buffer buf (cp.async; caller commits)
    auto stage = [&](int st, int buf) {
        const __half* Kb = Kbase + (size_t)(st << 6) * (NK * HD);
        const __half* Vb = Vbase + (st << 6);
        __half* dK = sK + buf * 8704;
        __half* dV = sVT + buf * 9216;
#pragma unroll
        for (int u = 0; u < 4; u++) {
            int cc = tid + (u << 8);
            int r = cc >> 4, ch = (cc & 15) << 3;
            cpa16(&dK[r * 136 + ch], Kb + (size_t)r * (NK * HD) + ch);
            int rv = cc >> 3, cv = (cc & 7) << 3;
            cpa16(&dV[rv * 72 + cv], Vb + (size_t)rv * Tt + cv);
        }
    };

    stage(0, 0);
    CP_COMMIT;

    for (int st = 0; st < ntile; st++) {
        const int s0 = st << 6;
        const int buf = st & 1;
        if (st + 1 < ntile) {
            stage(st + 1, buf ^ 1);
            CP_COMMIT;
            CP_WAIT(1);
        } else {
            CP_WAIT(0);
        }
        __syncthreads();

        if (s0 <= wmax) {
            const __half* sKb = sK + buf * 8704;
            const __half* sVb = sVT + buf * 9216;

            // S = Q @ K^T : warp m16 x n64, k=128
            float sacc[8][4];
#pragma unroll
            for (int i = 0; i < 8; i++)
#pragma unroll
                for (int j = 0; j < 4; j++) sacc[i][j] = 0.f;
#pragma unroll
            for (int kp = 0; kp < 8; kp++) {
#pragma unroll
                for (int np = 0; np < 4; np++) {
                    uint32_t bf[4];
                    ldsm4h(bf, &sKb[(np * 16 + b_row) * 136 + (kp << 4) + b_col]);
                    mma_f16(sacc[np * 2], qf[kp], bf[0], bf[1]);
                    mma_f16(sacc[np * 2 + 1], qf[kp], bf[2], bf[3]);
                }
            }

            // Mask + online softmax
            float mx0 = -1e30f, mx1 = -1e30f;
#pragma unroll
            for (int nt = 0; nt < 8; nt++) {
                int colb = s0 + (nt << 3) + (qd << 1);
                float v0 = sacc[nt][0] * scale;
                float v1 = sacc[nt][1] * scale;
                float v2 = sacc[nt][2] * scale;
                float v3 = sacc[nt][3] * scale;
                if (colb > row0)     v0 = -1e30f;
                if (colb + 1 > row0) v1 = -1e30f;
                if (colb > row1)     v2 = -1e30f;
                if (colb + 1 > row1) v3 = -1e30f;
                sacc[nt][0] = v0; sacc[nt][1] = v1; sacc[nt][2] = v2; sacc[nt][3] = v3;
                mx0 = fmaxf(mx0, fmaxf(v0, v1));
                mx1 = fmaxf(mx1, fmaxf(v2, v3));
            }
            mx0 = fmaxf(mx0, __shfl_xor_sync(0xffffffffu, mx0, 1));
            mx0 = fmaxf(mx0, __shfl_xor_sync(0xffffffffu, mx0, 2));
            mx1 = fmaxf(mx1, __shfl_xor_sync(0xffffffffu, mx1, 1));
            mx1 = fmaxf(mx1, __shfl_xor_sync(0xffffffffu, mx1, 2));
            float mn0 = fmaxf(m0, mx0), mn1 = fmaxf(m1, mx1);
            float a0 = __expf(m0 - mn0), a1 = __expf(m1 - mn1);
            m0 = mn0; m1 = mn1;
            float ps0 = 0.f, ps1 = 0.f;
#pragma unroll
            for (int nt = 0; nt < 8; nt++) {
                float p0 = __expf(sacc[nt][0] - m0);
                float p1 = __expf(sacc[nt][1] - m0);
                float p2 = __expf(sacc[nt][2] - m1);
                float p3 = __expf(sacc[nt][3] - m1);
                ps0 += p0 + p1; ps1 += p2 + p3;
                int col = (nt << 3) + (qd << 1);
                *(uint32_t*)&sPw[grp * 72 + col] = pack2(p0, p1);
                *(uint32_t*)&sPw[(grp + 8) * 72 + col] = pack2(p2, p3);
            }
            ps0 += __shfl_xor_sync(0xffffffffu, ps0, 1);
            ps0 += __shfl_xor_sync(0xffffffffu, ps0, 2);
            ps1 += __shfl_xor_sync(0xffffffffu, ps1, 1);
            ps1 += __shfl_xor_sync(0xffffffffu, ps1, 2);
            l0 = l0 * a0 + ps0;
            l1 = l1 * a1 + ps1;
#pragma unroll
            for (int nt = 0; nt < 16; nt++) {
                oacc[nt][0] *= a0; oacc[nt][1] *= a0;
                oacc[nt][2] *= a1; oacc[nt][3] *= a1;
            }
            __syncwarp();

            // O += P @ V : warp m16 x n128, k=64
#pragma unroll
            for (int kp = 0; kp < 4; kp++) {
                uint32_t af[4];
                ldsm4h(af, &sPw[a_row * 72 + (kp << 4) + a_col]);
#pragma unroll
                for (int np = 0; np < 8; np++) {
                    uint32_t bf[4];
                    ldsm4h(bf, &sVb[(np * 16 + b_row) * 72 + (kp << 4) + b_col]);
                    mma_f16(oacc[np * 2], af, bf[0], bf[1]);
                    mma_f16(oacc[np * 2 + 1], af, bf[2], bf[3]);
                }
            }
        }
        __syncthreads();
    }

    const float i0 = 1.0f / l0, i1 = 1.0f / l1;
    __half* Ob0 = O + ((size_t)(b * Tt + row0) * NQ + n) * HD;
    __half* Ob1 = O + ((size_t)(b * Tt + row1) * NQ + n) * HD;
#pragma unroll
    for (int nt = 0; nt < 16; nt++) {
        int col = (nt << 3) + (qd << 1);
        *(uint32_t*)(Ob0 + col) = pack2(oacc[nt][0] * i0, oacc[nt][1] * i0);
        *(uint32_t*)(Ob1 + col) = pack2(oacc[nt][2] * i1, oacc[nt][3] * i1);
    }
}

// ---------------------------------------------------------------------------
// Launch
// ---------------------------------------------------------------------------
extern "C" void kernel_launch(void* const* d_in, const int* in_sizes, int n_in,
                              void* d_out, int out_size) {
    (void)in_sizes; (void)n_in; (void)out_size;
    const float* x   = (const float*)d_in[0];
    const float* qw  = (const float*)d_in[1];
    const float* kw  = (const float*)d_in[2];
    const float* vw  = (const float*)d_in[3];
    const float* ow  = (const float*)d_in[4];
    const float* qnw = (const float*)d_in[5];
    const float* knw = (const float*)d_in[6];
    float* out = (float*)d_out;

    float *gq, *gk;
    __half *gxh, *gqh, *gkh, *gvt, *goh, *wtq, *wtk, *wtv, *wto;
    cudaGetSymbolAddress((void**)&gq, g_q);
    cudaGetSymbolAddress((void**)&gk, g_k);
    cudaGetSymbolAddress((void**)&gxh, g_xh);
    cudaGetSymbolAddress((void**)&gqh, g_qh);
    cudaGetSymbolAddress((void**)&gkh, g_kh);
    cudaGetSymbolAddress((void**)&gvt, g_vt);
    cudaGetSymbolAddress((void**)&goh, g_oh);
    cudaGetSymbolAddress((void**)&wtq, g_wtq);
    cudaGetSymbolAddress((void**)&wtk, g_wtk);
    cudaGetSymbolAddress((void**)&wtv, g_wtv);
    cudaGetSymbolAddress((void**)&wto, g_wto);

    const int M = MROWS;     // 4096
    const int NH = NQ * HD;  // 2048
    const int KHH = NK * HD; // 1024

    transpose_h<<<dim3(NH / 32, Dd / 32), 256>>>(qw, wtq, Dd, NH);
    transpose_h<<<dim3(KHH / 32, Dd / 32), 256>>>(kw, wtk, Dd, KHH);
    transpose_h<<<dim3(KHH / 32, Dd / 32), 256>>>(vw, wtv, Dd, KHH);
    transpose_h<<<dim3(Dd / 32, NH / 32), 256>>>(ow, wto, NH, Dd);
    cvt_half<<<(M * Dd) / 2048, 256>>>(x, gxh);

    gemm_h2<0><<<dim3(NH / 128, M / 128), 256>>>(gxh, wtq, gq, M, NH, Dd);
    gemm_h2<0><<<dim3(KHH / 128, M / 128), 256>>>(gxh, wtk, gk, M, KHH, Dd);
    gemm_h2<1><<<dim3(KHH / 128, M / 128), 256>>>(gxh, wtv, gvt, M, KHH, Dd);

    rope_table<<<(Tt * 64 + 255) / 256, 256>>>();
    rms_rope_v2<<<M * NQ / 8, 256>>>(gq, gqh, qnw, NQ);
    rms_rope_v2<<<M * NK / 8, 256>>>(gk, gkh, knw, NK);

    size_t smem = (size_t)(2 * 8704 + 2 * 9216 + 8 * 1152) * sizeof(__half); // 90112 B
    cudaFuncSetAttribute(flash_h2, cudaFuncAttributeMaxDynamicSharedMemorySize, (int)smem);
    flash_h2<<<dim3(Tt / 128, NQ, Bb), 256, smem>>>(gqh, gkh, gvt, goh);

    gemm_h2<0><<<dim3(Dd / 128, M / 128), 256>>>(goh, wto, out, M, Dd, NH);
}

// round 12
// speedup vs baseline: 5.6364x; 1.1373x over previous
#include <cuda_runtime.h>
#include <cuda_fp16.h>
#include <math.h>
#include <stdint.h>

#define Bb 2
#define Tt 2048
#define Dd 2048
#define NQ 16
#define NK 8
#define HD 128
#define MROWS (Bb * Tt)

// Scratch (device globals: allocation-free rule)
__device__ float  g_q[(size_t)MROWS * NQ * HD];     // fp32 Q proj (pre-norm)
__device__ float  g_k[(size_t)MROWS * NK * HD];     // fp32 K proj (pre-norm)
__device__ __half g_xh[(size_t)MROWS * Dd];         // half x
__device__ __half g_qh[(size_t)MROWS * NQ * HD];    // half Q (post rms+rope)
__device__ __half g_kh[(size_t)MROWS * NK * HD];    // half K (post rms+rope)
__device__ __half g_vt[(size_t)Bb * NK * HD * Tt];  // half V^T [b][kh][h][t]
__device__ __half g_oh[(size_t)MROWS * NQ * HD];    // half attention output
__device__ __half g_wqkv[4096 * 2048];              // [q_w^T; k_w^T; v_w^T]
__device__ __half g_wto[2048 * 2048];               // o_w^T [D][NH]
__device__ float  g_sin[Tt * 64];
__device__ float  g_cos[Tt * 64];

__device__ __forceinline__ uint32_t pack2(float a, float b) {
    __half2 h = __floats2half2_rn(a, b);
    return *(uint32_t*)&h;
}

__device__ __forceinline__ void mma_f16(float* d, const uint32_t* a,
                                        uint32_t b0, uint32_t b1) {
    asm volatile(
        "mma.sync.aligned.m16n8k16.row.col.f32.f16.f16.f32 "
        "{%0,%1,%2,%3}, {%4,%5,%6,%7}, {%8,%9}, {%0,%1,%2,%3};"
        : "+f"(d[0]), "+f"(d[1]), "+f"(d[2]), "+f"(d[3])
        : "r"(a[0]), "r"(a[1]), "r"(a[2]), "r"(a[3]), "r"(b0), "r"(b1));
}

__device__ __forceinline__ void ldsm4h(uint32_t* r, const __half* p) {
    uint32_t a = (uint32_t)__cvta_generic_to_shared(p);
    asm volatile("ldmatrix.sync.aligned.m8n8.x4.shared.b16 {%0,%1,%2,%3}, [%4];"
                 : "=r"(r[0]), "=r"(r[1]), "=r"(r[2]), "=r"(r[3]) : "r"(a));
}

__device__ __forceinline__ void cpa16(void* dst, const void* src) {
    uint32_t d = (uint32_t)__cvta_generic_to_shared(dst);
    asm volatile("cp.async.cg.shared.global [%0], [%1], 16;" :: "r"(d), "l"(src));
}
#define CP_COMMIT asm volatile("cp.async.commit_group;")
#define CP_WAIT(n) asm volatile("cp.async.wait_group %0;" :: "n"(n))

// ---------------------------------------------------------------------------
// fp32 -> fp16 bulk convert (8 elems/thread)
// ---------------------------------------------------------------------------
__global__ __launch_bounds__(256) void cvt_half(const float* __restrict__ in,
                                                __half* __restrict__ out) {
    size_t i = ((size_t)blockIdx.x * 256 + threadIdx.x) * 8;
    float4 a = *(const float4*)(in + i);
    float4 b = *(const float4*)(in + i + 4);
    uint4 w = make_uint4(pack2(a.x, a.y), pack2(a.z, a.w),
                         pack2(b.x, b.y), pack2(b.z, b.w));
    *(uint4*)(out + i) = w;
}

// ---------------------------------------------------------------------------
// Fused q/k/v weight transpose into g_wqkv [4096][2048] half.
// Concat col space: [0,2048)=q_w, [2048,3072)=k_w, [3072,4096)=v_w.
// ---------------------------------------------------------------------------
__global__ __launch_bounds__(256) void transpose_qkv(const float* __restrict__ qw,
                                                     const float* __restrict__ kw,
                                                     const float* __restrict__ vw,
                                                     __half* __restrict__ out) {
    __shared__ float t[32][33];
    const int colg = blockIdx.x << 5;      // concat col tile base
    const int by = blockIdx.y << 5;        // row tile base (Dd)
    const float* src;
    int srccol, C;
    if (colg < 2048)      { src = qw; srccol = colg;        C = 2048; }
    else if (colg < 3072) { src = kw; srccol = colg - 2048; C = 1024; }
    else                  { src = vw; srccol = colg - 3072; C = 1024; }
    const int tx = threadIdx.x & 31, ty = threadIdx.x >> 5;
#pragma unroll
    for (int i = 0; i < 32; i += 8)
        t[ty + i][tx] = src[(size_t)(by + ty + i) * C + srccol + tx];
    __syncthreads();
#pragma unroll
    for (int i = 0; i < 32; i += 8)
        out[(size_t)(colg + ty + i) * 2048 + by + tx] = __float2half(t[tx][ty + i]);
}

// ---------------------------------------------------------------------------
// fp32 -> half transpose for o_w: in[R][C] -> out[C][R]
// ---------------------------------------------------------------------------
__global__ __launch_bounds__(256) void transpose_h(const float* __restrict__ in,
                                                   __half* __restrict__ out,
                                                   int R, int C) {
    __shared__ float t[32][33];
    const int bx = blockIdx.x << 5, by = blockIdx.y << 5;
    const int tx = threadIdx.x & 31, ty = threadIdx.x >> 5;
#pragma unroll
    for (int i = 0; i < 32; i += 8)
        t[ty + i][tx] = in[(size_t)(by + ty + i) * C + bx + tx];
    __syncthreads();
#pragma unroll
    for (int i = 0; i < 32; i += 8)
        out[(size_t)(bx + ty + i) * R + by + tx] = __float2half(t[tx][ty + i]);
}

// ---------------------------------------------------------------------------
// fp16 GEMM, 4-stage cp.async ring, ONE __syncthreads per k-iteration.
// C[M,N] = A[M,K] @ BT[N,K]^T. Block 128x128x32, 256 threads, 8 warps.
// MODE 0: fp32 row-major C (Cq used as out, N arbitrary).
// MODE 1: fused QKV epilogue by col region: [0,2048) Q fp32, [2048,3072) K
//         fp32, [3072,4096) V half transposed into g_vt layout.
// Dynamic smem: 8 slots x 5120 halves = 81920 B.
// ---------------------------------------------------------------------------
template <int MODE>
__global__ __launch_bounds__(256) void gemm_h3(const __half* __restrict__ A,
                                               const __half* __restrict__ BT,
                                               float* __restrict__ Cq,
                                               float* __restrict__ Ck,
                                               __half* __restrict__ Cvt,
                                               int M, int N, int K) {
    extern __shared__ __half sm3[];
    __half* sA = sm3;             // 4 * 5120
    __half* sB = sm3 + 4 * 5120;  // 4 * 5120

    const int tid = threadIdx.x;
    const int bm = blockIdx.y << 7, bn = blockIdx.x << 7;
    const int warp = tid >> 5, lane = tid & 31;
    const int wm = (warp >> 2) << 6, wn = (warp & 3) << 5;
    const int grp = lane >> 2, qd = lane & 3;

    const int rs = tid >> 1;        // 0..127
    const int cb = (tid & 1) << 4;  // 0 or 16 halves

    const int a_row = (lane & 7) + ((lane >> 3) & 1) * 8;
    const int a_col = ((lane >> 4) & 1) * 8;
    const int b_row = (lane & 7) + ((lane >> 4) & 1) * 8;
    const int b_col = ((lane >> 3) & 1) * 8;

    float acc[4][4][4];
#pragma unroll
    for (int i = 0; i < 4; i++)
#pragma unroll
        for (int j = 0; j < 4; j++)
#pragma unroll
            for (int r = 0; r < 4; r++) acc[i][j][r] = 0.f;

    const __half* Ap = A + (size_t)(bm + rs) * K + cb;
    const __half* Bp = BT + (size_t)(bn + rs) * K + cb;
    const int soff = rs * 40 + cb;

    const int nkt = K >> 5;
    // prologue: stage tiles 0..2
#pragma unroll
    for (int s = 0; s < 3; s++) {
        const int k0 = s << 5;
        cpa16(&sA[s * 5120 + soff], Ap + k0);
        cpa16(&sA[s * 5120 + soff + 8], Ap + k0 + 8);
        cpa16(&sB[s * 5120 + soff], Bp + k0);
        cpa16(&sB[s * 5120 + soff + 8], Bp + k0 + 8);
        CP_COMMIT;
    }

    for (int kt = 0; kt < nkt; kt++) {
        const int slot = kt & 3;
        CP_WAIT(2);            // group kt complete (always 3 groups in flight)
        __syncthreads();       // all threads done with slot (kt-1)&3 reads
        if (kt + 3 < nkt) {    // stage kt+3 into slot (kt+3)&3 == (kt-1)&3
            const int k0 = (kt + 3) << 5;
            const int ns = (kt + 3) & 3;
            cpa16(&sA[ns * 5120 + soff], Ap + k0);
            cpa16(&sA[ns * 5120 + soff + 8], Ap + k0 + 8);
            cpa16(&sB[ns * 5120 + soff], Bp + k0);
            cpa16(&sB[ns * 5120 + soff + 8], Bp + k0 + 8);
        }
        CP_COMMIT;             // one group per iteration (possibly empty)

        const __half* sAb = sA + slot * 5120;
        const __half* sBb = sB + slot * 5120;
#pragma unroll
        for (int ks = 0; ks < 2; ks++) {
            uint32_t af[4][4], bf[2][4];
#pragma unroll
            for (int mt = 0; mt < 4; mt++)
                ldsm4h(af[mt], &sAb[(wm + mt * 16 + a_row) * 40 + ks * 16 + a_col]);
#pragma unroll
            for (int np = 0; np < 2; np++)
                ldsm4h(bf[np], &sBb[(wn + np * 16 + b_row) * 40 + ks * 16 + b_col]);
#pragma unroll
            for (int mt = 0; mt < 4; mt++)
#pragma unroll
                for (int nt = 0; nt < 4; nt++)
                    mma_f16(acc[mt][nt], af[mt],
                            bf[nt >> 1][(nt & 1) * 2], bf[nt >> 1][(nt & 1) * 2 + 1]);
        }
    }

    if (MODE == 0 || bn < 3072) {
        float* C;
        int col0, NN;
        if (MODE == 0) { C = Cq; col0 = bn; NN = N; }
        else if (bn < 2048) { C = Cq; col0 = bn; NN = 2048; }
        else { C = Ck; col0 = bn - 2048; NN = 1024; }
#pragma unroll
        for (int mt = 0; mt < 4; mt++)
#pragma unroll
            for (int nt = 0; nt < 4; nt++) {
                int row = bm + wm + (mt << 4) + grp;
                int col = col0 + wn + (nt << 3) + (qd << 1);
                *(float2*)(C + (size_t)row * NN + col) =
                    make_float2(acc[mt][nt][0], acc[mt][nt][1]);
                *(float2*)(C + (size_t)(row + 8) * NN + col) =
                    make_float2(acc[mt][nt][2], acc[mt][nt][3]);
            }
    } else {
        // V region: half, transposed into [b][kh*HD+h][t]
#pragma unroll
        for (int mt = 0; mt < 4; mt++)
#pragma unroll
            for (int nt = 0; nt < 4; nt++) {
                int row = bm + wm + (mt << 4) + grp;
                int col = (bn - 3072) + wn + (nt << 3) + (qd << 1);
                int b = row >> 11, t = row & 2047;
                size_t base0 = ((size_t)b * NK * HD + col) * Tt + t;
                size_t base1 = ((size_t)b * NK * HD + col + 1) * Tt + t;
                Cvt[base0] = __float2half(acc[mt][nt][0]);
                Cvt[base1] = __float2half(acc[mt][nt][1]);
                Cvt[base0 + 8] = __float2half(acc[mt][nt][2]);
                Cvt[base1 + 8] = __float2half(acc[mt][nt][3]);
            }
    }
}

// ---------------------------------------------------------------------------
// RoPE table
// ---------------------------------------------------------------------------
__global__ __launch_bounds__(256) void rope_table() {
    int idx = blockIdx.x * 256 + threadIdx.x;
    if (idx >= Tt * 64) return;
    int t = idx >> 6, i = idx & 63;
    double ang = (double)t * exp(-0.21586735246819178 * (double)i);
    double s, c;
    sincos(ang, &s, &c);
    g_sin[idx] = (float)s;
    g_cos[idx] = (float)c;
}

// ---------------------------------------------------------------------------
// Fused RMSNorm + RoPE v2: 1 warp per (row, head), float4, no smem/syncs.
// ---------------------------------------------------------------------------
__global__ __launch_bounds__(256) void rms_rope_v2(const float* __restrict__ in,
                                                   __half* __restrict__ outb,
                                                   const float* __restrict__ w,
                                                   int heads) {
    const int gw = blockIdx.x * 8 + (threadIdx.x >> 5);
    const int lane = threadIdx.x & 31;
    const int t = (gw / heads) % Tt;

    float4 x = *(const float4*)(in + (size_t)gw * HD + lane * 4);
    float ss = x.x * x.x + x.y * x.y + x.z * x.z + x.w * x.w;
#pragma unroll
    for (int off = 16; off; off >>= 1) ss += __shfl_xor_sync(0xffffffffu, ss, off);
    float rinv = rsqrtf(ss * (1.0f / (float)HD) + 1e-6f);

    float4 wv = *(const float4*)(w + lane * 4);
    float y[4] = {wv.x * x.x * rinv, wv.y * x.y * rinv,
                  wv.z * x.z * rinv, wv.w * x.w * rinv};
    float yp[4];
#pragma unroll
    for (int j = 0; j < 4; j++) yp[j] = __shfl_xor_sync(0xffffffffu, y[j], 16);

    const int i0 = ((lane & 15) << 2);
    float o[4];
#pragma unroll
    for (int j = 0; j < 4; j++) {
        float s = g_sin[t * 64 + i0 + j];
        float c = g_cos[t * 64 + i0 + j];
        o[j] = (lane < 16) ? (y[j] * c - yp[j] * s) : (y[j] * c + yp[j] * s);
    }
    uint2 pk = make_uint2(pack2(o[0], o[1]), pack2(o[2], o[3]));
    *(uint2*)(outb + (size_t)gw * HD + lane * 4) = pk;
}

// ---------------------------------------------------------------------------
// Flash attention fp16, s-tile 64, cp.async double-buffered K/V.
// 256 threads (8 warps), q-tile 128 (warp = 16 rows, Q frags in regs).
// Dynamic smem: sK 2x[64][136], sVT 2x[128][72], sP 8x[16][72]  (90112 B)
// ---------------------------------------------------------------------------
__global__ __launch_bounds__(256) void flash_h2(const __half* __restrict__ Q,
                                                const __half* __restrict__ Kc,
                                                const __half* __restrict__ VT,
                                                __half* __restrict__ O) {
    extern __shared__ __half smh[];
    __half* sK = smh;                  // 2 * 8704
    __half* sVT = sK + 2 * 8704;       // 2 * 9216
    __half* sP = sVT + 2 * 9216;       // 8 * 1152

    const int tid = threadIdx.x;
    const int w = tid >> 5, lane = tid & 31;
    const int grp = lane >> 2, qd = lane & 3;
    const int b = blockIdx.z, n = blockIdx.y;
    const int qt = blockIdx.x << 7;
    const int kh = n >> 1;

    const int a_row = (lane & 7) + ((lane >> 3) & 1) * 8;
    const int a_col = ((lane >> 4) & 1) * 8;
    const int b_row = (lane & 7) + ((lane >> 4) & 1) * 8;
    const int b_col = ((lane >> 3) & 1) * 8;

    // Load Q fragments into registers (staged through sK, 64-row chunks)
    uint32_t qf[8][4];
    {
        const __half* Qb = Q + ((size_t)(b * Tt + qt) * NQ + n) * HD;
#pragma unroll
        for (int c = 0; c < 2; c++) {
            __half* sKc = sK + c * 8704;
#pragma unroll
            for (int u = 0; u < 4; u++) {
                int cc = tid + (u << 8);
                int r = cc >> 4, ch = (cc & 15) << 3;
                *(uint4*)&sKc[r * 136 + ch] =
                    *(const uint4*)(Qb + (size_t)(c * 64 + r) * (NQ * HD) + ch);
            }
            __syncthreads();
            if ((w >> 2) == c) {
                const int lr = ((w & 3) << 4) + a_row;
#pragma unroll
                for (int kp = 0; kp < 8; kp++)
                    ldsm4h(qf[kp], &sKc[lr * 136 + (kp << 4) + a_col]);
            }
            __syncthreads();
        }
    }

    float oacc[16][4];
#pragma unroll
    for (int i = 0; i < 16; i++)
#pragma unroll
        for (int j = 0; j < 4; j++) oacc[i][j] = 0.f;
    float m0 = -1e30f, m1 = -1e30f, l0 = 0.f, l1 = 0.f;

    const float scale = 0.08838834764831845f;
    const int row0 = qt + (w << 4) + grp;
    const int row1 = row0 + 8;
    const int wmax = qt + (w << 4) + 15;
    const int ntile = (qt >> 6) + 2;
    __half* sPw = sP + w * 1152;

    const __half* Kbase = Kc + ((size_t)b * Tt * NK + kh) * HD;
    const __half* Vbase = VT + ((size_t)(b * NK + kh) * HD) * Tt;

    auto stage = [&](int st, int buf) {
        const __half* Kb = Kbase + (size_t)(st << 6) * (NK * HD);
        const __half* Vb = Vbase + (st << 6);
        __half* dK = sK + buf * 8704;
        __half* dV = sVT + buf * 9216;
#pragma unroll
        for (int u = 0; u < 4; u++) {
            int cc = tid + (u << 8);
            int r = cc >> 4, ch = (cc & 15) << 3;
            cpa16(&dK[r * 136 + ch], Kb + (size_t)r * (NK * HD) + ch);
            int rv = cc >> 3, cv = (cc & 7) << 3;
            cpa16(&dV[rv * 72 + cv], Vb + (size_t)rv * Tt + cv);
        }
    };

    stage(0, 0);
    CP_COMMIT;

    for (int st = 0; st < ntile; st++) {
        const int s0 = st << 6;
        const int buf = st & 1;
        if (st + 1 < ntile) {
            stage(st + 1, buf ^ 1);
            CP_COMMIT;
            CP_WAIT(1);
        } else {
            CP_WAIT(0);
        }
        __syncthreads();

        if (s0 <= wmax) {
            const __half* sKb = sK + buf * 8704;
            const __half* sVb = sVT + buf * 9216;

            float sacc[8][4];
#pragma unroll
            for (int i = 0; i < 8; i++)
#pragma unroll
                for (int j = 0; j < 4; j++) sacc[i][j] = 0.f;
#pragma unroll
            for (int kp = 0; kp < 8; kp++) {
#pragma unroll
                for (int np = 0; np < 4; np++) {
                    uint32_t bf[4];
                    ldsm4h(bf, &sKb[(np * 16 + b_row) * 136 + (kp << 4) + b_col]);
                    mma_f16(sacc[np * 2], qf[kp], bf[0], bf[1]);
                    mma_f16(sacc[np * 2 + 1], qf[kp], bf[2], bf[3]);
                }
            }

            float mx0 = -1e30f, mx1 = -1e30f;
#pragma unroll
            for (int nt = 0; nt < 8; nt++) {
                int colb = s0 + (nt << 3) + (qd << 1);
                float v0 = sacc[nt][0] * scale;
                float v1 = sacc[nt][1] * scale;
                float v2 = sacc[nt][2] * scale;
                float v3 = sacc[nt][3] * scale;
                if (colb > row0)     v0 = -1e30f;
                if (colb + 1 > row0) v1 = -1e30f;
                if (colb > row1)     v2 = -1e30f;
                if (colb + 1 > row1) v3 = -1e30f;
                sacc[nt][0] = v0; sacc[nt][1] = v1; sacc[nt][2] = v2; sacc[nt][3] = v3;
                mx0 = fmaxf(mx0, fmaxf(v0, v1));
                mx1 = fmaxf(mx1, fmaxf(v2, v3));
            }
            mx0 = fmaxf(mx0, __shfl_xor_sync(0xffffffffu, mx0, 1));
            mx0 = fmaxf(mx0, __shfl_xor_sync(0xffffffffu, mx0, 2));
            mx1 = fmaxf(mx1, __shfl_xor_sync(0xffffffffu, mx1, 1));
            mx1 = fmaxf(mx1, __shfl_xor_sync(0xffffffffu, mx1, 2));
            float mn0 = fmaxf(m0, mx0), mn1 = fmaxf(m1, mx1);
            float a0 = __expf(m0 - mn0), a1 = __expf(m1 - mn1);
            m0 = mn0; m1 = mn1;
            float ps0 = 0.f, ps1 = 0.f;
#pragma unroll
            for (int nt = 0; nt < 8; nt++) {
                float p0 = __expf(sacc[nt][0] - m0);
                float p1 = __expf(sacc[nt][1] - m0);
                float p2 = __expf(sacc[nt][2] - m1);
                float p3 = __expf(sacc[nt][3] - m1);
                ps0 += p0 + p1; ps1 += p2 + p3;
                int col = (nt << 3) + (qd << 1);
                *(uint32_t*)&sPw[grp * 72 + col] = pack2(p0, p1);
                *(uint32_t*)&sPw[(grp + 8) * 72 + col] = pack2(p2, p3);
            }
            ps0 += __shfl_xor_sync(0xffffffffu, ps0, 1);
            ps0 += __shfl_xor_sync(0xffffffffu, ps0, 2);
            ps1 += __shfl_xor_sync(0xffffffffu, ps1, 1);
            ps1 += __shfl_xor_sync(0xffffffffu, ps1, 2);
            l0 = l0 * a0 + ps0;
            l1 = l1 * a1 + ps1;
#pragma unroll
            for (int nt = 0; nt < 16; nt++) {
                oacc[nt][0] *= a0; oacc[nt][1] *= a0;
                oacc[nt][2] *= a1; oacc[nt][3] *= a1;
            }
            __syncwarp();

#pragma unroll
            for (int kp = 0; kp < 4; kp++) {
                uint32_t af[4];
                ldsm4h(af, &sPw[a_row * 72 + (kp << 4) + a_col]);
#pragma unroll
                for (int np = 0; np < 8; np++) {
                    uint32_t bf[4];
                    ldsm4h(bf, &sVb[(np * 16 + b_row) * 72 + (kp << 4) + b_col]);
                    mma_f16(oacc[np * 2], af, bf[0], bf[1]);
                    mma_f16(oacc[np * 2 + 1], af, bf[2], bf[3]);
                }
            }
        }
        __syncthreads();
    }

    const float i0 = 1.0f / l0, i1 = 1.0f / l1;
    __half* Ob0 = O + ((size_t)(b * Tt + row0) * NQ + n) * HD;
    __half* Ob1 = O + ((size_t)(b * Tt + row1) * NQ + n) * HD;
#pragma unroll
    for (int nt = 0; nt < 16; nt++) {
        int col = (nt << 3) + (qd << 1);
        *(uint32_t*)(Ob0 + col) = pack2(oacc[nt][0] * i0, oacc[nt][1] * i0);
        *(uint32_t*)(Ob1 + col) = pack2(oacc[nt][2] * i1, oacc[nt][3] * i1);
    }
}

// ---------------------------------------------------------------------------
// Launch (order chosen so launch #4 = fused QKV GEMM, which ncu profiles)
// ---------------------------------------------------------------------------
extern "C" void kernel_launch(void* const* d_in, const int* in_sizes, int n_in,
                              void* d_out, int out_size) {
    (void)in_sizes; (void)n_in; (void)out_size;
    const float* x   = (const float*)d_in[0];
    const float* qw  = (const float*)d_in[1];
    const float* kw  = (const float*)d_in[2];
    const float* vw  = (const float*)d_in[3];
    const float* ow  = (const float*)d_in[4];
    const float* qnw = (const float*)d_in[5];
    const float* knw = (const float*)d_in[6];
    float* out = (float*)d_out;

    float *gq, *gk;
    __half *gxh, *gqh, *gkh, *gvt, *goh, *wqkv, *wto;
    cudaGetSymbolAddress((void**)&gq, g_q);
    cudaGetSymbolAddress((void**)&gk, g_k);
    cudaGetSymbolAddress((void**)&gxh, g_xh);
    cudaGetSymbolAddress((void**)&gqh, g_qh);
    cudaGetSymbolAddress((void**)&gkh, g_kh);
    cudaGetSymbolAddress((void**)&gvt, g_vt);
    cudaGetSymbolAddress((void**)&goh, g_oh);
    cudaGetSymbolAddress((void**)&wqkv, g_wqkv);
    cudaGetSymbolAddress((void**)&wto, g_wto);

    const int M = MROWS;     // 4096
    const int NH = NQ * HD;  // 2048

    const size_t gsmem = 81920;
    cudaFuncSetAttribute(gemm_h3<0>, cudaFuncAttributeMaxDynamicSharedMemorySize, (int)gsmem);
    cudaFuncSetAttribute(gemm_h3<1>, cudaFuncAttributeMaxDynamicSharedMemorySize, (int)gsmem);

    // 1: x -> half
    cvt_half<<<(M * Dd) / 2048, 256>>>(x, gxh);
    // 2: fused qkv weight transpose
    transpose_qkv<<<dim3(128, 64), 256>>>(qw, kw, vw, wqkv);
    // 3: rope table
    rope_table<<<(Tt * 64 + 255) / 256, 256>>>();
    // 4: fused QKV projection (profiled)
    gemm_h3<1><<<dim3(32, 32), 256, gsmem>>>(gxh, wqkv, gq, gk, gvt, M, 4096, Dd);
    // 5-6: rms+rope
    rms_rope_v2<<<M * NQ / 8, 256>>>(gq, gqh, qnw, NQ);
    rms_rope_v2<<<M * NK / 8, 256>>>(gk, gkh, knw, NK);
    // 7: o_w transpose
    transpose_h<<<dim3(Dd / 32, NH / 32), 256>>>(ow, wto, NH, Dd);
    // 8: flash attention
    size_t fsmem = (size_t)(2 * 8704 + 2 * 9216 + 8 * 1152) * sizeof(__half); // 90112
    cudaFuncSetAttribute(flash_h2, cudaFuncAttributeMaxDynamicSharedMemorySize, (int)fsmem);
    flash_h2<<<dim3(Tt / 128, NQ, Bb), 256, fsmem>>>(gqh, gkh, gvt, goh);
    // 9: output projection
    gemm_h3<0><<<dim3(Dd / 128, M / 128), 256, gsmem>>>(goh, wto, out, nullptr, nullptr, M, Dd, NH);
}

// round 14
// speedup vs baseline: 5.7623x; 1.0223x over previous
#include <cuda_runtime.h>
#include <cuda_fp16.h>
#include <math.h>
#include <stdint.h>

#define Bb 2
#define Tt 2048
#define Dd 2048
#define NQ 16
#define NK 8
#define HD 128
#define MROWS (Bb * Tt)

// Scratch (device globals: allocation-free rule)
__device__ __half g_xh[(size_t)MROWS * Dd];         // half x
__device__ __half g_qh[(size_t)MROWS * NQ * HD];    // half Q (post rms+rope)
__device__ __half g_kh[(size_t)MROWS * NK * HD];    // half K (post rms+rope)
__device__ __half g_vt[(size_t)Bb * NK * HD * Tt];  // half V^T [b][kh][h][t]
__device__ __half g_oh[(size_t)MROWS * NQ * HD];    // half attention output
__device__ __half g_wqkv[4096 * 2048];              // [q_w^T; k_w^T; v_w^T]
__device__ __half g_wto[2048 * 2048];               // o_w^T [D][NH]
__device__ float  g_sin[Tt * 64];
__device__ float  g_cos[Tt * 64];

__device__ __forceinline__ uint32_t pack2(float a, float b) {
    __half2 h = __floats2half2_rn(a, b);
    return *(uint32_t*)&h;
}

__device__ __forceinline__ void mma_f16(float* d, const uint32_t* a,
                                        uint32_t b0, uint32_t b1) {
    asm volatile(
        "mma.sync.aligned.m16n8k16.row.col.f32.f16.f16.f32 "
        "{%0,%1,%2,%3}, {%4,%5,%6,%7}, {%8,%9}, {%0,%1,%2,%3};"
        : "+f"(d[0]), "+f"(d[1]), "+f"(d[2]), "+f"(d[3])
        : "r"(a[0]), "r"(a[1]), "r"(a[2]), "r"(a[3]), "r"(b0), "r"(b1));
}

__device__ __forceinline__ void ldsm4h(uint32_t* r, const __half* p) {
    uint32_t a = (uint32_t)__cvta_generic_to_shared(p);
    asm volatile("ldmatrix.sync.aligned.m8n8.x4.shared.b16 {%0,%1,%2,%3}, [%4];"
                 : "=r"(r[0]), "=r"(r[1]), "=r"(r[2]), "=r"(r[3]) : "r"(a));
}

__device__ __forceinline__ void cpa16(void* dst, const void* src) {
    uint32_t d = (uint32_t)__cvta_generic_to_shared(dst);
    asm volatile("cp.async.cg.shared.global [%0], [%1], 16;" :: "r"(d), "l"(src));
}
#define CP_COMMIT asm volatile("cp.async.commit_group;")
#define CP_WAIT(n) asm volatile("cp.async.wait_group %0;" :: "n"(n))

// ---------------------------------------------------------------------------
// fp32 -> fp16 bulk convert (8 elems/thread)
// ---------------------------------------------------------------------------
__global__ __launch_bounds__(256) void cvt_half(const float* __restrict__ in,
                                                __half* __restrict__ out) {
    size_t i = ((size_t)blockIdx.x * 256 + threadIdx.x) * 8;
    float4 a = *(const float4*)(in + i);
    float4 b = *(const float4*)(in + i + 4);
    uint4 w = make_uint4(pack2(a.x, a.y), pack2(a.z, a.w),
                         pack2(b.x, b.y), pack2(b.z, b.w));
    *(uint4*)(out + i) = w;
}

// ---------------------------------------------------------------------------
// Fused q/k/v weight transpose into g_wqkv [4096][2048] half.
// ---------------------------------------------------------------------------
__global__ __launch_bounds__(256) void transpose_qkv(const float* __restrict__ qw,
                                                     const float* __restrict__ kw,
                                                     const float* __restrict__ vw,
                                                     __half* __restrict__ out) {
    __shared__ float t[32][33];
    const int colg = blockIdx.x << 5;
    const int by = blockIdx.y << 5;
    const float* src;
    int srccol, C;
    if (colg < 2048)      { src = qw; srccol = colg;        C = 2048; }
    else if (colg < 3072) { src = kw; srccol = colg - 2048; C = 1024; }
    else                  { src = vw; srccol = colg - 3072; C = 1024; }
    const int tx = threadIdx.x & 31, ty = threadIdx.x >> 5;
#pragma unroll
    for (int i = 0; i < 32; i += 8)
        t[ty + i][tx] = src[(size_t)(by + ty + i) * C + srccol + tx];
    __syncthreads();
#pragma unroll
    for (int i = 0; i < 32; i += 8)
        out[(size_t)(colg + ty + i) * 2048 + by + tx] = __float2half(t[tx][ty + i]);
}

// ---------------------------------------------------------------------------
// fp32 -> half transpose for o_w
// ---------------------------------------------------------------------------
__global__ __launch_bounds__(256) void transpose_h(const float* __restrict__ in,
                                                   __half* __restrict__ out,
                                                   int R, int C) {
    __shared__ float t[32][33];
    const int bx = blockIdx.x << 5, by = blockIdx.y << 5;
    const int tx = threadIdx.x & 31, ty = threadIdx.x >> 5;
#pragma unroll
    for (int i = 0; i < 32; i += 8)
        t[ty + i][tx] = in[(size_t)(by + ty + i) * C + bx + tx];
    __syncthreads();
#pragma unroll
    for (int i = 0; i < 32; i += 8)
        out[(size_t)(bx + ty + i) * R + by + tx] = __float2half(t[tx][ty + i]);
}

// ---------------------------------------------------------------------------
// RoPE table
// ---------------------------------------------------------------------------
__global__ __launch_bounds__(256) void rope_table() {
    int idx = blockIdx.x * 256 + threadIdx.x;
    if (idx >= Tt * 64) return;
    int t = idx >> 6, i = idx & 63;
    double ang = (double)t * exp(-0.21586735246819178 * (double)i);
    double s, c;
    sincos(ang, &s, &c);
    g_sin[idx] = (float)s;
    g_cos[idx] = (float)c;
}

// ---------------------------------------------------------------------------
// fp16 GEMM, 4-stage cp.async ring, one __syncthreads per k-iteration.
// C = A[M,K] @ BT[N,K]^T. Block 128x128x32, 256 threads, 8 warps (2m x 4n).
// MODE 0: fp32 row-major out C0 (width N).
// MODE 1: fused QKV epilogue. bn in [0,2048): Q -> rms+rope -> half g_qh.
//         [2048,3072): K -> rms+rope -> half g_kh. [3072,4096): V -> half
//         transposed g_vt. One 128-col block tile == one head, so the block
//         holds complete head vectors: norm is block-local.
// Dynamic smem: 8 slots x 5120 halves = 81920 B (epilogue reuses as fp32 ytile)
// ---------------------------------------------------------------------------
template <int MODE>
__global__ __launch_bounds__(256) void gemm_h4(const __half* __restrict__ A,
                                               const __half* __restrict__ BT,
                                               float* __restrict__ C0,
                                               __half* __restrict__ Qh,
                                               __half* __restrict__ Kh,
                                               __half* __restrict__ Vt,
                                               const float* __restrict__ qnw,
                                               const float* __restrict__ knw,
                                               int M, int N, int K) {
    extern __shared__ __half sm3[];
    __half* sA = sm3;             // 4 * 5120
    __half* sB = sm3 + 4 * 5120;  // 4 * 5120

    const int tid = threadIdx.x;
    const int bm = blockIdx.y << 7, bn = blockIdx.x << 7;
    const int warp = tid >> 5, lane = tid & 31;
    const int wm = (warp >> 2) << 6, wn = (warp & 3) << 5;
    const int grp = lane >> 2, qd = lane & 3;

    const int rs = tid >> 1;        // 0..127
    const int cb = (tid & 1) << 4;  // 0 or 16 halves

    const int a_row = (lane & 7) + ((lane >> 3) & 1) * 8;
    const int a_col = ((lane >> 4) & 1) * 8;
    const int b_row = (lane & 7) + ((lane >> 4) & 1) * 8;
    const int b_col = ((lane >> 3) & 1) * 8;

    float acc[4][4][4];
#pragma unroll
    for (int i = 0; i < 4; i++)
#pragma unroll
        for (int j = 0; j < 4; j++)
#pragma unroll
            for (int r = 0; r < 4; r++) acc[i][j][r] = 0.f;

    const __half* Ap = A + (size_t)(bm + rs) * K + cb;
    const __half* Bp = BT + (size_t)(bn + rs) * K + cb;
    const int soff = rs * 40 + cb;

    const int nkt = K >> 5;
#pragma unroll
    for (int s = 0; s < 3; s++) {
        const int k0 = s << 5;
        cpa16(&sA[s * 5120 + soff], Ap + k0);
        cpa16(&sA[s * 5120 + soff + 8], Ap + k0 + 8);
        cpa16(&sB[s * 5120 + soff], Bp + k0);
        cpa16(&sB[s * 5120 + soff + 8], Bp + k0 + 8);
        CP_COMMIT;
    }

    for (int kt = 0; kt < nkt; kt++) {
        const int slot = kt & 3;
        CP_WAIT(2);
        __syncthreads();
        if (kt + 3 < nkt) {
            const int k0 = (kt + 3) << 5;
            const int ns = (kt + 3) & 3;
            cpa16(&sA[ns * 5120 + soff], Ap + k0);
            cpa16(&sA[ns * 5120 + soff + 8], Ap + k0 + 8);
            cpa16(&sB[ns * 5120 + soff], Bp + k0);
            cpa16(&sB[ns * 5120 + soff + 8], Bp + k0 + 8);
        }
        CP_COMMIT;

        const __half* sAb = sA + slot * 5120;
        const __half* sBb = sB + slot * 5120;
#pragma unroll
        for (int ks = 0; ks < 2; ks++) {
            uint32_t af[4][4], bf[2][4];
#pragma unroll
            for (int mt = 0; mt < 4; mt++)
                ldsm4h(af[mt], &sAb[(wm + mt * 16 + a_row) * 40 + ks * 16 + a_col]);
#pragma unroll
            for (int np = 0; np < 2; np++)
                ldsm4h(bf[np], &sBb[(wn + np * 16 + b_row) * 40 + ks * 16 + b_col]);
#pragma unroll
            for (int mt = 0; mt < 4; mt++)
#pragma unroll
                for (int nt = 0; nt < 4; nt++)
                    mma_f16(acc[mt][nt], af[mt],
                            bf[nt >> 1][(nt & 1) * 2], bf[nt >> 1][(nt & 1) * 2 + 1]);
        }
    }

    if (MODE == 0) {
#pragma unroll
        for (int mt = 0; mt < 4; mt++)
#pragma unroll
            for (int nt = 0; nt < 4; nt++) {
                int row = bm + wm + (mt << 4) + grp;
                int col = bn + wn + (nt << 3) + (qd << 1);
                *(float2*)(C0 + (size_t)row * N + col) =
                    make_float2(acc[mt][nt][0], acc[mt][nt][1]);
                *(float2*)(C0 + (size_t)(row + 8) * N + col) =
                    make_float2(acc[mt][nt][2], acc[mt][nt][3]);
            }
    } else if (bn >= 3072) {
        // V region: half, transposed into [b][kh*HD+h][t]
#pragma unroll
        for (int mt = 0; mt < 4; mt++)
#pragma unroll
            for (int nt = 0; nt < 4; nt++) {
                int row = bm + wm + (mt << 4) + grp;
                int col = (bn - 3072) + wn + (nt << 3) + (qd << 1);
                int b = row >> 11, t = row & 2047;
                size_t base0 = ((size_t)b * NK * HD + col) * Tt + t;
                size_t base1 = ((size_t)b * NK * HD + col + 1) * Tt + t;
                Vt[base0] = __float2half(acc[mt][nt][0]);
                Vt[base1] = __float2half(acc[mt][nt][1]);
                Vt[base0 + 8] = __float2half(acc[mt][nt][2]);
                Vt[base1 + 8] = __float2half(acc[mt][nt][3]);
            }
    } else {
        // Q/K region: fused RMSNorm + RoPE. Stage acc to smem fp32.
        __syncthreads();  // mainloop readers of staging smem done
        float* yt = (float*)sm3;  // 128 x 132 fp32 = 67584 B <= 81920
#pragma unroll
        for (int mt = 0; mt < 4; mt++)
#pragma unroll
            for (int nt = 0; nt < 4; nt++) {
                int row = wm + (mt << 4) + grp;
                int col = wn + (nt << 3) + (qd << 1);
                yt[row * 132 + col] = acc[mt][nt][0];
                yt[row * 132 + col + 1] = acc[mt][nt][1];
                yt[(row + 8) * 132 + col] = acc[mt][nt][2];
                yt[(row + 8) * 132 + col + 1] = acc[mt][nt][3];
            }
        __syncthreads();

        const float* wvec = (bn < 2048) ? qnw : knw;
        const int row = tid >> 1, hf = tid & 1;
        const float* yr = yt + row * 132;

        float ss = 0.f;
#pragma unroll
        for (int c = 0; c < 64; c += 4) {
            float4 v = *(const float4*)(yr + hf * 64 + c);
            ss += v.x * v.x + v.y * v.y + v.z * v.z + v.w * v.w;
        }
        ss += __shfl_xor_sync(0xffffffffu, ss, 1);
        const float rinv = rsqrtf(ss * (1.0f / (float)HD) + 1e-6f);

        const int grow = bm + row;
        const int b = grow >> 11, t = grow & 2047;
        __half* dst;
        if (bn < 2048) dst = Qh + ((size_t)(b * Tt + t) * NQ + (bn >> 7)) * HD;
        else           dst = Kh + ((size_t)(b * Tt + t) * NK + ((bn - 2048) >> 7)) * HD;
        const float* srow = g_sin + t * 64;
        const float* crow = g_cos + t * 64;

#pragma unroll
        for (int c0 = 0; c0 < 64; c0 += 4) {
            const int c = hf * 64 + c0;
            float4 yv = *(const float4*)(yr + c);
            float4 pv = *(const float4*)(yr + (c ^ 64));
            float4 wv = *(const float4*)(wvec + c);
            float4 wp = *(const float4*)(wvec + (c ^ 64));
            float4 sv = *(const float4*)(srow + c0);
            float4 cv = *(const float4*)(crow + c0);
            float y0 = wv.x * yv.x * rinv, p0 = wp.x * pv.x * rinv;
            float y1 = wv.y * yv.y * rinv, p1 = wp.y * pv.y * rinv;
            float y2 = wv.z * yv.z * rinv, p2 = wp.z * pv.z * rinv;
            float y3 = wv.w * yv.w * rinv, p3 = wp.w * pv.w * rinv;
            float o0, o1, o2, o3;
            if (hf == 0) {
                o0 = y0 * cv.x - p0 * sv.x; o1 = y1 * cv.y - p1 * sv.y;
                o2 = y2 * cv.z - p2 * sv.z; o3 = y3 * cv.w - p3 * sv.w;
            } else {
                o0 = y0 * cv.x + p0 * sv.x; o1 = y1 * cv.y + p1 * sv.y;
                o2 = y2 * cv.z + p2 * sv.z; o3 = y3 * cv.w + p3 * sv.w;
            }
            *(uint2*)(dst + c) = make_uint2(pack2(o0, o1), pack2(o2, o3));
        }
    }
}

// ---------------------------------------------------------------------------
// Flash attention fp16 mma.sync, s-tile 64, cp.async double-buffered K/V.
// ---------------------------------------------------------------------------
__global__ __launch_bounds__(256) void flash_h2(const __half* __restrict__ Q,
                                                const __half* __restrict__ Kc,
                                                const __half* __restrict__ VT,
                                                __half* __restrict__ O) {
    extern __shared__ __half smh[];
    __half* sK = smh;                  // 2 * 8704
    __half* sVT = sK + 2 * 8704;       // 2 * 9216
    __half* sP = sVT + 2 * 9216;       // 8 * 1152

    const int tid = threadIdx.x;
    const int w = tid >> 5, lane = tid & 31;
    const int grp = lane >> 2, qd = lane & 3;
    const int b = blockIdx.z, n = blockIdx.y;
    const int qt = blockIdx.x << 7;
    const int kh = n >> 1;

    const int a_row = (lane & 7) + ((lane >> 3) & 1) * 8;
    const int a_col = ((lane >> 4) & 1) * 8;
    const int b_row = (lane & 7) + ((lane >> 4) & 1) * 8;
    const int b_col = ((lane >> 3) & 1) * 8;

    uint32_t qf[8][4];
    {
        const __half* Qb = Q + ((size_t)(b * Tt + qt) * NQ + n) * HD;
#pragma unroll
        for (int c = 0; c < 2; c++) {
            __half* sKc = sK + c * 8704;
#pragma unroll
            for (int u = 0; u < 4; u++) {
                int cc = tid + (u << 8);
                int r = cc >> 4, ch = (cc & 15) << 3;
                *(uint4*)&sKc[r * 136 + ch] =
                    *(const uint4*)(Qb + (size_t)(c * 64 + r) * (NQ * HD) + ch);
            }
            __syncthreads();
            if ((w >> 2) == c) {
                const int lr = ((w & 3) << 4) + a_row;
#pragma unroll
                for (int kp = 0; kp < 8; kp++)
                    ldsm4h(qf[kp], &sKc[lr * 136 + (kp << 4) + a_col]);
            }
            __syncthreads();
        }
    }

    float oacc[16][4];
#pragma unroll
    for (int i = 0; i < 16; i++)
#pragma unroll
        for (int j = 0; j < 4; j++) oacc[i][j] = 0.f;
    float m0 = -1e30f, m1 = -1e30f, l0 = 0.f, l1 = 0.f;

    const float scale = 0.08838834764831845f;
    const int row0 = qt + (w << 4) + grp;
    const int row1 = row0 + 8;
    const int wmax = qt + (w << 4) + 15;
    const int ntile = (qt >> 6) + 2;
    __half* sPw = sP + w * 1152;

    const __half* Kbase = Kc + ((size_t)b * Tt * NK + kh) * HD;
    const __half* Vbase = VT + ((size_t)(b * NK + kh) * HD) * Tt;

    auto stage = [&](int st, int buf) {
        const __half* Kb = Kbase + (size_t)(st << 6) * (NK * HD);
        const __half* Vb = Vbase + (st << 6);
        __half* dK = sK + buf * 8704;
        __half* dV = sVT + buf * 9216;
#pragma unroll
        for (int u = 0; u < 4; u++) {
            int cc = tid + (u << 8);
            int r = cc >> 4, ch = (cc & 15) << 3;
            cpa16(&dK[r * 136 + ch], Kb + (size_t)r * (NK * HD) + ch);
            int rv = cc >> 3, cv = (cc & 7) << 3;
            cpa16(&dV[rv * 72 + cv], Vb + (size_t)rv * Tt + cv);
        }
    };

    stage(0, 0);
    CP_COMMIT;

    for (int st = 0; st < ntile; st++) {
        const int s0 = st << 6;
        const int buf = st & 1;
        if (st + 1 < ntile) {
            stage(st + 1, buf ^ 1);
            CP_COMMIT;
            CP_WAIT(1);
        } else {
            CP_WAIT(0);
        }
        __syncthreads();

        if (s0 <= wmax) {
            const __half* sKb = sK + buf * 8704;
            const __half* sVb = sVT + buf * 9216;

            float sacc[8][4];
#pragma unroll
            for (int i = 0; i < 8; i++)
#pragma unroll
                for (int j = 0; j < 4; j++) sacc[i][j] = 0.f;
#pragma unroll
            for (int kp = 0; kp < 8; kp++) {
#pragma unroll
                for (int np = 0; np < 4; np++) {
                    uint32_t bf[4];
                    ldsm4h(bf, &sKb[(np * 16 + b_row) * 136 + (kp << 4) + b_col]);
                    mma_f16(sacc[np * 2], qf[kp], bf[0], bf[1]);
                    mma_f16(sacc[np * 2 + 1], qf[kp], bf[2], bf[3]);
                }
            }

            float mx0 = -1e30f, mx1 = -1e30f;
#pragma unroll
            for (int nt = 0; nt < 8; nt++) {
                int colb = s0 + (nt << 3) + (qd << 1);
                float v0 = sacc[nt][0] * scale;
                float v1 = sacc[nt][1] * scale;
                float v2 = sacc[nt][2] * scale;
                float v3 = sacc[nt][3] * scale;
                if (colb > row0)     v0 = -1e30f;
                if (colb + 1 > row0) v1 = -1e30f;
                if (colb > row1)     v2 = -1e30f;
                if (colb + 1 > row1) v3 = -1e30f;
                sacc[nt][0] = v0; sacc[nt][1] = v1; sacc[nt][2] = v2; sacc[nt][3] = v3;
                mx0 = fmaxf(mx0, fmaxf(v0, v1));
                mx1 = fmaxf(mx1, fmaxf(v2, v3));
            }
            mx0 = fmaxf(mx0, __shfl_xor_sync(0xffffffffu, mx0, 1));
            mx0 = fmaxf(mx0, __shfl_xor_sync(0xffffffffu, mx0, 2));
            mx1 = fmaxf(mx1, __shfl_xor_sync(0xffffffffu, mx1, 1));
            mx1 = fmaxf(mx1, __shfl_xor_sync(0xffffffffu, mx1, 2));
            float mn0 = fmaxf(m0, mx0), mn1 = fmaxf(m1, mx1);
            float a0 = __expf(m0 - mn0), a1 = __expf(m1 - mn1);
            m0 = mn0; m1 = mn1;
            float ps0 = 0.f, ps1 = 0.f;
#pragma unroll
            for (int nt = 0; nt < 8; nt++) {
                float p0 = __expf(sacc[nt][0] - m0);
                float p1 = __expf(sacc[nt][1] - m0);
                float p2 = __expf(sacc[nt][2] - m1);
                float p3 = __expf(sacc[nt][3] - m1);
                ps0 += p0 + p1; ps1 += p2 + p3;
                int col = (nt << 3) + (qd << 1);
                *(uint32_t*)&sPw[grp * 72 + col] = pack2(p0, p1);
                *(uint32_t*)&sPw[(grp + 8) * 72 + col] = pack2(p2, p3);
            }
            ps0 += __shfl_xor_sync(0xffffffffu, ps0, 1);
            ps0 += __shfl_xor_sync(0xffffffffu, ps0, 2);
            ps1 += __shfl_xor_sync(0xffffffffu, ps1, 1);
            ps1 += __shfl_xor_sync(0xffffffffu, ps1, 2);
            l0 = l0 * a0 + ps0;
            l1 = l1 * a1 + ps1;
#pragma unroll
            for (int nt = 0; nt < 16; nt++) {
                oacc[nt][0] *= a0; oacc[nt][1] *= a0;
                oacc[nt][2] *= a1; oacc[nt][3] *= a1;
            }
            __syncwarp();

#pragma unroll
            for (int kp = 0; kp < 4; kp++) {
                uint32_t af[4];
                ldsm4h(af, &sPw[a_row * 72 + (kp << 4) + a_col]);
#pragma unroll
                for (int np = 0; np < 8; np++) {
                    uint32_t bf[4];
                    ldsm4h(bf, &sVb[(np * 16 + b_row) * 72 + (kp << 4) + b_col]);
                    mma_f16(oacc[np * 2], af, bf[0], bf[1]);
                    mma_f16(oacc[np * 2 + 1], af, bf[2], bf[3]);
                }
            }
        }
        __syncthreads();
    }

    const float i0 = 1.0f / l0, i1 = 1.0f / l1;
    __half* Ob0 = O + ((size_t)(b * Tt + row0) * NQ + n) * HD;
    __half* Ob1 = O + ((size_t)(b * Tt + row1) * NQ + n) * HD;
#pragma unroll
    for (int nt = 0; nt < 16; nt++) {
        int col = (nt << 3) + (qd << 1);
        *(uint32_t*)(Ob0 + col) = pack2(oacc[nt][0] * i0, oacc[nt][1] * i0);
        *(uint32_t*)(Ob1 + col) = pack2(oacc[nt][2] * i1, oacc[nt][3] * i1);
    }
}

// ---------------------------------------------------------------------------
// Launch (launch #4 = fused QKV GEMM, profiled by ncu)
// ---------------------------------------------------------------------------
extern "C" void kernel_launch(void* const* d_in, const int* in_sizes, int n_in,
                              void* d_out, int out_size) {
    (void)in_sizes; (void)n_in; (void)out_size;
    const float* x   = (const float*)d_in[0];
    const float* qw  = (const float*)d_in[1];
    const float* kw  = (const float*)d_in[2];
    const float* vw  = (const float*)d_in[3];
    const float* ow  = (const float*)d_in[4];
    const float* qnw = (const float*)d_in[5];
    const float* knw = (const float*)d_in[6];
    float* out = (float*)d_out;

    __half *gxh, *gqh, *gkh, *gvt, *goh, *wqkv, *wto;
    cudaGetSymbolAddress((void**)&gxh, g_xh);
    cudaGetSymbolAddress((void**)&gqh, g_qh);
    cudaGetSymbolAddress((void**)&gkh, g_kh);
    cudaGetSymbolAddress((void**)&gvt, g_vt);
    cudaGetSymbolAddress((void**)&goh, g_oh);
    cudaGetSymbolAddress((void**)&wqkv, g_wqkv);
    cudaGetSymbolAddress((void**)&wto, g_wto);

    const int M = MROWS;     // 4096
    const int NH = NQ * HD;  // 2048

    const size_t gsmem = 81920;
    cudaFuncSetAttribute(gemm_h4<0>, cudaFuncAttributeMaxDynamicSharedMemorySize, (int)gsmem);
    cudaFuncSetAttribute(gemm_h4<1>, cudaFuncAttributeMaxDynamicSharedMemorySize, (int)gsmem);

    // 1: x -> half
    cvt_half<<<(M * Dd) / 2048, 256>>>(x, gxh);
    // 2: fused qkv weight transpose
    transpose_qkv<<<dim3(128, 64), 256>>>(qw, kw, vw, wqkv);
    // 3: rope table (must precede fused epilogue)
    rope_table<<<(Tt * 64 + 255) / 256, 256>>>();
    // 4: fused QKV projection + rms + rope + V-transpose (profiled)
    gemm_h4<1><<<dim3(32, 32), 256, gsmem>>>(gxh, wqkv, nullptr, gqh, gkh, gvt,
                                             qnw, knw, M, 4096, Dd);
    // 5: o_w transpose
    transpose_h<<<dim3(Dd / 32, NH / 32), 256>>>(ow, wto, NH, Dd);
    // 6: flash attention
    size_t fsmem = (size_t)(2 * 8704 + 2 * 9216 + 8 * 1152) * sizeof(__half); // 90112
    cudaFuncSetAttribute(flash_h2, cudaFuncAttributeMaxDynamicSharedMemorySize, (int)fsmem);
    flash_h2<<<dim3(Tt / 128, NQ, Bb), 256, fsmem>>>(gqh, gkh, gvt, goh);
    // 7: output projection
    gemm_h4<0><<<dim3(Dd / 128, M / 128), 256, gsmem>>>(goh, wto, out, nullptr, nullptr,
                                                        nullptr, nullptr, nullptr, M, Dd, NH);
}

// round 15
// speedup vs baseline: 5.8800x; 1.0204x over previous
#include <cuda_runtime.h>
#include <cuda_fp16.h>
#include <math.h>
#include <stdint.h>

#define Bb 2
#define Tt 2048
#define Dd 2048
#define NQ 16
#define NK 8
#define HD 128
#define MROWS (Bb * Tt)

// Scratch (device globals: allocation-free rule)
__device__ __half g_xh[(size_t)MROWS * Dd];         // half x
__device__ __half g_qh[(size_t)MROWS * NQ * HD];    // half Q (post rms+rope)
__device__ __half g_kh[(size_t)MROWS * NK * HD];    // half K (post rms+rope)
__device__ __half g_vt[(size_t)Bb * NK * HD * Tt];  // half V^T [b][kh][h][t]
__device__ __half g_oh[(size_t)MROWS * NQ * HD];    // half attention output
__device__ __half g_wqkv[4096 * 2048];              // [q_w^T; k_w^T; v_w^T]
__device__ __half g_wto[2048 * 2048];               // o_w^T [D][NH]
__device__ float  g_sin[Tt * 64];
__device__ float  g_cos[Tt * 64];

__device__ __forceinline__ uint32_t pack2(float a, float b) {
    __half2 h = __floats2half2_rn(a, b);
    return *(uint32_t*)&h;
}

__device__ __forceinline__ void mma_f16(float* d, const uint32_t* a,
                                        uint32_t b0, uint32_t b1) {
    asm volatile(
        "mma.sync.aligned.m16n8k16.row.col.f32.f16.f16.f32 "
        "{%0,%1,%2,%3}, {%4,%5,%6,%7}, {%8,%9}, {%0,%1,%2,%3};"
        : "+f"(d[0]), "+f"(d[1]), "+f"(d[2]), "+f"(d[3])
        : "r"(a[0]), "r"(a[1]), "r"(a[2]), "r"(a[3]), "r"(b0), "r"(b1));
}

__device__ __forceinline__ void ldsm4h(uint32_t* r, const __half* p) {
    uint32_t a = (uint32_t)__cvta_generic_to_shared(p);
    asm volatile("ldmatrix.sync.aligned.m8n8.x4.shared.b16 {%0,%1,%2,%3}, [%4];"
                 : "=r"(r[0]), "=r"(r[1]), "=r"(r[2]), "=r"(r[3]) : "r"(a));
}

__device__ __forceinline__ void cpa16(void* dst, const void* src) {
    uint32_t d = (uint32_t)__cvta_generic_to_shared(dst);
    asm volatile("cp.async.cg.shared.global [%0], [%1], 16;" :: "r"(d), "l"(src));
}
#define CP_COMMIT asm volatile("cp.async.commit_group;")
#define CP_WAIT(n) asm volatile("cp.async.wait_group %0;" :: "n"(n))

// ---------------------------------------------------------------------------
// fp32 -> fp16 bulk convert (8 elems/thread)
// ---------------------------------------------------------------------------
__global__ __launch_bounds__(256) void cvt_half(const float* __restrict__ in,
                                                __half* __restrict__ out) {
    size_t i = ((size_t)blockIdx.x * 256 + threadIdx.x) * 8;
    float4 a = *(const float4*)(in + i);
    float4 b = *(const float4*)(in + i + 4);
    uint4 w = make_uint4(pack2(a.x, a.y), pack2(a.z, a.w),
                         pack2(b.x, b.y), pack2(b.z, b.w));
    *(uint4*)(out + i) = w;
}

// ---------------------------------------------------------------------------
// Fused q/k/v weight transpose into g_wqkv [4096][2048] half.
// ---------------------------------------------------------------------------
__global__ __launch_bounds__(256) void transpose_qkv(const float* __restrict__ qw,
                                                     const float* __restrict__ kw,
                                                     const float* __restrict__ vw,
                                                     __half* __restrict__ out) {
    __shared__ float t[32][33];
    const int colg = blockIdx.x << 5;
    const int by = blockIdx.y << 5;
    const float* src;
    int srccol, C;
    if (colg < 2048)      { src = qw; srccol = colg;        C = 2048; }
    else if (colg < 3072) { src = kw; srccol = colg - 2048; C = 1024; }
    else                  { src = vw; srccol = colg - 3072; C = 1024; }
    const int tx = threadIdx.x & 31, ty = threadIdx.x >> 5;
#pragma unroll
    for (int i = 0; i < 32; i += 8)
        t[ty + i][tx] = src[(size_t)(by + ty + i) * C + srccol + tx];
    __syncthreads();
#pragma unroll
    for (int i = 0; i < 32; i += 8)
        out[(size_t)(colg + ty + i) * 2048 + by + tx] = __float2half(t[tx][ty + i]);
}

// ---------------------------------------------------------------------------
// fp32 -> half transpose for o_w
// ---------------------------------------------------------------------------
__global__ __launch_bounds__(256) void transpose_h(const float* __restrict__ in,
                                                   __half* __restrict__ out,
                                                   int R, int C) {
    __shared__ float t[32][33];
    const int bx = blockIdx.x << 5, by = blockIdx.y << 5;
    const int tx = threadIdx.x & 31, ty = threadIdx.x >> 5;
#pragma unroll
    for (int i = 0; i < 32; i += 8)
        t[ty + i][tx] = in[(size_t)(by + ty + i) * C + bx + tx];
    __syncthreads();
#pragma unroll
    for (int i = 0; i < 32; i += 8)
        out[(size_t)(bx + ty + i) * R + by + tx] = __float2half(t[tx][ty + i]);
}

// ---------------------------------------------------------------------------
// RoPE table
// ---------------------------------------------------------------------------
__global__ __launch_bounds__(256) void rope_table() {
    int idx = blockIdx.x * 256 + threadIdx.x;
    if (idx >= Tt * 64) return;
    int t = idx >> 6, i = idx & 63;
    double ang = (double)t * exp(-0.21586735246819178 * (double)i);
    double s, c;
    sincos(ang, &s, &c);
    g_sin[idx] = (float)s;
    g_cos[idx] = (float)c;
}

// ---------------------------------------------------------------------------
// fp16 GEMM, 3-stage cp.async ring, one __syncthreads per k-iteration,
// __launch_bounds__(256,2) -> 2 blocks/SM (regs capped at 128).
// C = A[M,K] @ BT[N,K]^T. Block 128x128x32, 8 warps (2m x 4n).
// MODE 0: fp32 row-major out C0 (width N). smem 61440 B.
// MODE 1: fused QKV epilogue (Q/K rms+rope -> half; V -> half transposed).
//         smem request 67584 B (epilogue fp32 ytile 128x132).
// ---------------------------------------------------------------------------
template <int MODE>
__global__ __launch_bounds__(256, 2) void gemm_h5(const __half* __restrict__ A,
                                                  const __half* __restrict__ BT,
                                                  float* __restrict__ C0,
                                                  __half* __restrict__ Qh,
                                                  __half* __restrict__ Kh,
                                                  __half* __restrict__ Vt,
                                                  const float* __restrict__ qnw,
                                                  const float* __restrict__ knw,
                                                  int M, int N, int K) {
    extern __shared__ __half sm3[];
    __half* sA = sm3;             // 3 * 5120
    __half* sB = sm3 + 3 * 5120;  // 3 * 5120

    const int tid = threadIdx.x;
    const int bm = blockIdx.y << 7, bn = blockIdx.x << 7;
    const int warp = tid >> 5, lane = tid & 31;
    const int wm = (warp >> 2) << 6, wn = (warp & 3) << 5;
    const int grp = lane >> 2, qd = lane & 3;

    const int rs = tid >> 1;        // 0..127
    const int cb = (tid & 1) << 4;  // 0 or 16 halves

    const int a_row = (lane & 7) + ((lane >> 3) & 1) * 8;
    const int a_col = ((lane >> 4) & 1) * 8;
    const int b_row = (lane & 7) + ((lane >> 4) & 1) * 8;
    const int b_col = ((lane >> 3) & 1) * 8;

    float acc[4][4][4];
#pragma unroll
    for (int i = 0; i < 4; i++)
#pragma unroll
        for (int j = 0; j < 4; j++)
#pragma unroll
            for (int r = 0; r < 4; r++) acc[i][j][r] = 0.f;

    const __half* Ap = A + (size_t)(bm + rs) * K + cb;
    const __half* Bp = BT + (size_t)(bn + rs) * K + cb;
    const int soff = rs * 40 + cb;

    const int nkt = K >> 5;
    // prologue: stage tiles 0,1
#pragma unroll
    for (int s = 0; s < 2; s++) {
        const int k0 = s << 5;
        cpa16(&sA[s * 5120 + soff], Ap + k0);
        cpa16(&sA[s * 5120 + soff + 8], Ap + k0 + 8);
        cpa16(&sB[s * 5120 + soff], Bp + k0);
        cpa16(&sB[s * 5120 + soff + 8], Bp + k0 + 8);
        CP_COMMIT;
    }

    int slot = 0;
    for (int kt = 0; kt < nkt; kt++) {
        CP_WAIT(1);            // group kt complete (one newer may be pending)
        __syncthreads();       // all threads done reading the slot we re-stage
        if (kt + 2 < nkt) {
            const int k0 = (kt + 2) << 5;
            const int ns = (slot + 2 >= 3) ? slot - 1 : slot + 2;
            cpa16(&sA[ns * 5120 + soff], Ap + k0);
            cpa16(&sA[ns * 5120 + soff + 8], Ap + k0 + 8);
            cpa16(&sB[ns * 5120 + soff], Bp + k0);
            cpa16(&sB[ns * 5120 + soff + 8], Bp + k0 + 8);
        }
        CP_COMMIT;             // one group per iteration (possibly empty)

        const __half* sAb = sA + slot * 5120;
        const __half* sBb = sB + slot * 5120;
#pragma unroll
        for (int ks = 0; ks < 2; ks++) {
            uint32_t af[4][4], bf[2][4];
#pragma unroll
            for (int mt = 0; mt < 4; mt++)
                ldsm4h(af[mt], &sAb[(wm + mt * 16 + a_row) * 40 + ks * 16 + a_col]);
#pragma unroll
            for (int np = 0; np < 2; np++)
                ldsm4h(bf[np], &sBb[(wn + np * 16 + b_row) * 40 + ks * 16 + b_col]);
#pragma unroll
            for (int mt = 0; mt < 4; mt++)
#pragma unroll
                for (int nt = 0; nt < 4; nt++)
                    mma_f16(acc[mt][nt], af[mt],
                            bf[nt >> 1][(nt & 1) * 2], bf[nt >> 1][(nt & 1) * 2 + 1]);
        }
        slot = (slot + 1 >= 3) ? 0 : slot + 1;
    }

    if (MODE == 0) {
#pragma unroll
        for (int mt = 0; mt < 4; mt++)
#pragma unroll
            for (int nt = 0; nt < 4; nt++) {
                int row = bm + wm + (mt << 4) + grp;
                int col = bn + wn + (nt << 3) + (qd << 1);
                *(float2*)(C0 + (size_t)row * N + col) =
                    make_float2(acc[mt][nt][0], acc[mt][nt][1]);
                *(float2*)(C0 + (size_t)(row + 8) * N + col) =
                    make_float2(acc[mt][nt][2], acc[mt][nt][3]);
            }
    } else if (bn >= 3072) {
        // V region: half, transposed into [b][kh*HD+h][t]
#pragma unroll
        for (int mt = 0; mt < 4; mt++)
#pragma unroll
            for (int nt = 0; nt < 4; nt++) {
                int row = bm + wm + (mt << 4) + grp;
                int col = (bn - 3072) + wn + (nt << 3) + (qd << 1);
                int b = row >> 11, t = row & 2047;
                size_t base0 = ((size_t)b * NK * HD + col) * Tt + t;
                size_t base1 = ((size_t)b * NK * HD + col + 1) * Tt + t;
                Vt[base0] = __float2half(acc[mt][nt][0]);
                Vt[base1] = __float2half(acc[mt][nt][1]);
                Vt[base0 + 8] = __float2half(acc[mt][nt][2]);
                Vt[base1 + 8] = __float2half(acc[mt][nt][3]);
            }
    } else {
        // Q/K region: fused RMSNorm + RoPE via fp32 smem ytile.
        __syncthreads();
        float* yt = (float*)sm3;  // 128 x 132 fp32 = 67584 B
#pragma unroll
        for (int mt = 0; mt < 4; mt++)
#pragma unroll
            for (int nt = 0; nt < 4; nt++) {
                int row = wm + (mt << 4) + grp;
                int col = wn + (nt << 3) + (qd << 1);
                yt[row * 132 + col] = acc[mt][nt][0];
                yt[row * 132 + col + 1] = acc[mt][nt][1];
                yt[(row + 8) * 132 + col] = acc[mt][nt][2];
                yt[(row + 8) * 132 + col + 1] = acc[mt][nt][3];
            }
        __syncthreads();

        const float* wvec = (bn < 2048) ? qnw : knw;
        const int row = tid >> 1, hf = tid & 1;
        const float* yr = yt + row * 132;

        float ss = 0.f;
#pragma unroll
        for (int c = 0; c < 64; c += 4) {
            float4 v = *(const float4*)(yr + hf * 64 + c);
            ss += v.x * v.x + v.y * v.y + v.z * v.z + v.w * v.w;
        }
        ss += __shfl_xor_sync(0xffffffffu, ss, 1);
        const float rinv = rsqrtf(ss * (1.0f / (float)HD) + 1e-6f);

        const int grow = bm + row;
        const int b = grow >> 11, t = grow & 2047;
        __half* dst;
        if (bn < 2048) dst = Qh + ((size_t)(b * Tt + t) * NQ + (bn >> 7)) * HD;
        else           dst = Kh + ((size_t)(b * Tt + t) * NK + ((bn - 2048) >> 7)) * HD;
        const float* srow = g_sin + t * 64;
        const float* crow = g_cos + t * 64;

#pragma unroll
        for (int c0 = 0; c0 < 64; c0 += 4) {
            const int c = hf * 64 + c0;
            float4 yv = *(const float4*)(yr + c);
            float4 pv = *(const float4*)(yr + (c ^ 64));
            float4 wv = *(const float4*)(wvec + c);
            float4 wp = *(const float4*)(wvec + (c ^ 64));
            float4 sv = *(const float4*)(srow + c0);
            float4 cv = *(const float4*)(crow + c0);
            float y0 = wv.x * yv.x * rinv, p0 = wp.x * pv.x * rinv;
            float y1 = wv.y * yv.y * rinv, p1 = wp.y * pv.y * rinv;
            float y2 = wv.z * yv.z * rinv, p2 = wp.z * pv.z * rinv;
            float y3 = wv.w * yv.w * rinv, p3 = wp.w * pv.w * rinv;
            float o0, o1, o2, o3;
            if (hf == 0) {
                o0 = y0 * cv.x - p0 * sv.x; o1 = y1 * cv.y - p1 * sv.y;
                o2 = y2 * cv.z - p2 * sv.z; o3 = y3 * cv.w - p3 * sv.w;
            } else {
                o0 = y0 * cv.x + p0 * sv.x; o1 = y1 * cv.y + p1 * sv.y;
                o2 = y2 * cv.z + p2 * sv.z; o3 = y3 * cv.w + p3 * sv.w;
            }
            *(uint2*)(dst + c) = make_uint2(pack2(o0, o1), pack2(o2, o3));
        }
    }
}

// ---------------------------------------------------------------------------
// Flash attention fp16 mma.sync, s-tile 64, cp.async double-buffered K/V.
// ---------------------------------------------------------------------------
__global__ __launch_bounds__(256) void flash_h2(const __half* __restrict__ Q,
                                                const __half* __restrict__ Kc,
                                                const __half* __restrict__ VT,
                                                __half* __restrict__ O) {
    extern __shared__ __half smh[];
    __half* sK = smh;                  // 2 * 8704
    __half* sVT = sK + 2 * 8704;       // 2 * 9216
    __half* sP = sVT + 2 * 9216;       // 8 * 1152

    const int tid = threadIdx.x;
    const int w = tid >> 5, lane = tid & 31;
    const int grp = lane >> 2, qd = lane & 3;
    const int b = blockIdx.z, n = blockIdx.y;
    const int qt = blockIdx.x << 7;
    const int kh = n >> 1;

    const int a_row = (lane & 7) + ((lane >> 3) & 1) * 8;
    const int a_col = ((lane >> 4) & 1) * 8;
    const int b_row = (lane & 7) + ((lane >> 4) & 1) * 8;
    const int b_col = ((lane >> 3) & 1) * 8;

    uint32_t qf[8][4];
    {
        const __half* Qb = Q + ((size_t)(b * Tt + qt) * NQ + n) * HD;
#pragma unroll
        for (int c = 0; c < 2; c++) {
            __half* sKc = sK + c * 8704;
#pragma unroll
            for (int u = 0; u < 4; u++) {
                int cc = tid + (u << 8);
                int r = cc >> 4, ch = (cc & 15) << 3;
                *(uint4*)&sKc[r * 136 + ch] =
                    *(const uint4*)(Qb + (size_t)(c * 64 + r) * (NQ * HD) + ch);
            }
            __syncthreads();
            if ((w >> 2) == c) {
                const int lr = ((w & 3) << 4) + a_row;
#pragma unroll
                for (int kp = 0; kp < 8; kp++)
                    ldsm4h(qf[kp], &sKc[lr * 136 + (kp << 4) + a_col]);
            }
            __syncthreads();
        }
    }

    float oacc[16][4];
#pragma unroll
    for (int i = 0; i < 16; i++)
#pragma unroll
        for (int j = 0; j < 4; j++) oacc[i][j] = 0.f;
    float m0 = -1e30f, m1 = -1e30f, l0 = 0.f, l1 = 0.f;

    const float scale = 0.08838834764831845f;
    const int row0 = qt + (w << 4) + grp;
    const int row1 = row0 + 8;
    const int wmax = qt + (w << 4) + 15;
    const int ntile = (qt >> 6) + 2;
    __half* sPw = sP + w * 1152;

    const __half* Kbase = Kc + ((size_t)b * Tt * NK + kh) * HD;
    const __half* Vbase = VT + ((size_t)(b * NK + kh) * HD) * Tt;

    auto stage = [&](int st, int buf) {
        const __half* Kb = Kbase + (size_t)(st << 6) * (NK * HD);
        const __half* Vb = Vbase + (st << 6);
        __half* dK = sK + buf * 8704;
        __half* dV = sVT + buf * 9216;
#pragma unroll
        for (int u = 0; u < 4; u++) {
            int cc = tid + (u << 8);
            int r = cc >> 4, ch = (cc & 15) << 3;
            cpa16(&dK[r * 136 + ch], Kb + (size_t)r * (NK * HD) + ch);
            int rv = cc >> 3, cv = (cc & 7) << 3;
            cpa16(&dV[rv * 72 + cv], Vb + (size_t)rv * Tt + cv);
        }
    };

    stage(0, 0);
    CP_COMMIT;

    for (int st = 0; st < ntile; st++) {
        const int s0 = st << 6;
        const int buf = st & 1;
        if (st + 1 < ntile) {
            stage(st + 1, buf ^ 1);
            CP_COMMIT;
            CP_WAIT(1);
        } else {
            CP_WAIT(0);
        }
        __syncthreads();

        if (s0 <= wmax) {
            const __half* sKb = sK + buf * 8704;
            const __half* sVb = sVT + buf * 9216;

            float sacc[8][4];
#pragma unroll
            for (int i = 0; i < 8; i++)
#pragma unroll
                for (int j = 0; j < 4; j++) sacc[i][j] = 0.f;
#pragma unroll
            for (int kp = 0; kp < 8; kp++) {
#pragma unroll
                for (int np = 0; np < 4; np++) {
                    uint32_t bf[4];
                    ldsm4h(bf, &sKb[(np * 16 + b_row) * 136 + (kp << 4) + b_col]);
                    mma_f16(sacc[np * 2], qf[kp], bf[0], bf[1]);
                    mma_f16(sacc[np * 2 + 1], qf[kp], bf[2], bf[3]);
                }
            }

            float mx0 = -1e30f, mx1 = -1e30f;
#pragma unroll
            for (int nt = 0; nt < 8; nt++) {
                int colb = s0 + (nt << 3) + (qd << 1);
                float v0 = sacc[nt][0] * scale;
                float v1 = sacc[nt][1] * scale;
                float v2 = sacc[nt][2] * scale;
                float v3 = sacc[nt][3] * scale;
                if (colb > row0)     v0 = -1e30f;
                if (colb + 1 > row0) v1 = -1e30f;
                if (colb > row1)     v2 = -1e30f;
                if (colb + 1 > row1) v3 = -1e30f;
                sacc[nt][0] = v0; sacc[nt][1] = v1; sacc[nt][2] = v2; sacc[nt][3] = v3;
                mx0 = fmaxf(mx0, fmaxf(v0, v1));
                mx1 = fmaxf(mx1, fmaxf(v2, v3));
            }
            mx0 = fmaxf(mx0, __shfl_xor_sync(0xffffffffu, mx0, 1));
            mx0 = fmaxf(mx0, __shfl_xor_sync(0xffffffffu, mx0, 2));
            mx1 = fmaxf(mx1, __shfl_xor_sync(0xffffffffu, mx1, 1));
            mx1 = fmaxf(mx1, __shfl_xor_sync(0xffffffffu, mx1, 2));
            float mn0 = fmaxf(m0, mx0), mn1 = fmaxf(m1, mx1);
            float a0 = __expf(m0 - mn0), a1 = __expf(m1 - mn1);
            m0 = mn0; m1 = mn1;
            float ps0 = 0.f, ps1 = 0.f;
#pragma unroll
            for (int nt = 0; nt < 8; nt++) {
                float p0 = __expf(sacc[nt][0] - m0);
                float p1 = __expf(sacc[nt][1] - m0);
                float p2 = __expf(sacc[nt][2] - m1);
                float p3 = __expf(sacc[nt][3] - m1);
                ps0 += p0 + p1; ps1 += p2 + p3;
                int col = (nt << 3) + (qd << 1);
                *(uint32_t*)&sPw[grp * 72 + col] = pack2(p0, p1);
                *(uint32_t*)&sPw[(grp + 8) * 72 + col] = pack2(p2, p3);
            }
            ps0 += __shfl_xor_sync(0xffffffffu, ps0, 1);
            ps0 += __shfl_xor_sync(0xffffffffu, ps0, 2);
            ps1 += __shfl_xor_sync(0xffffffffu, ps1, 1);
            ps1 += __shfl_xor_sync(0xffffffffu, ps1, 2);
            l0 = l0 * a0 + ps0;
            l1 = l1 * a1 + ps1;
#pragma unroll
            for (int nt = 0; nt < 16; nt++) {
                oacc[nt][0] *= a0; oacc[nt][1] *= a0;
                oacc[nt][2] *= a1; oacc[nt][3] *= a1;
            }
            __syncwarp();

#pragma unroll
            for (int kp = 0; kp < 4; kp++) {
                uint32_t af[4];
                ldsm4h(af, &sPw[a_row * 72 + (kp << 4) + a_col]);
#pragma unroll
                for (int np = 0; np < 8; np++) {
                    uint32_t bf[4];
                    ldsm4h(bf, &sVb[(np * 16 + b_row) * 72 + (kp << 4) + b_col]);
                    mma_f16(oacc[np * 2], af, bf[0], bf[1]);
                    mma_f16(oacc[np * 2 + 1], af, bf[2], bf[3]);
                }
            }
        }
        __syncthreads();
    }

    const float i0 = 1.0f / l0, i1 = 1.0f / l1;
    __half* Ob0 = O + ((size_t)(b * Tt + row0) * NQ + n) * HD;
    __half* Ob1 = O + ((size_t)(b * Tt + row1) * NQ + n) * HD;
#pragma unroll
    for (int nt = 0; nt < 16; nt++) {
        int col = (nt << 3) + (qd << 1);
        *(uint32_t*)(Ob0 + col) = pack2(oacc[nt][0] * i0, oacc[nt][1] * i0);
        *(uint32_t*)(Ob1 + col) = pack2(oacc[nt][2] * i1, oacc[nt][3] * i1);
    }
}

// ---------------------------------------------------------------------------
// Launch (launch #4 = fused QKV GEMM, profiled by ncu)
// ---------------------------------------------------------------------------
extern "C" void kernel_launch(void* const* d_in, const int* in_sizes, int n_in,
                              void* d_out, int out_size) {
    (void)in_sizes; (void)n_in; (void)out_size;
    const float* x   = (const float*)d_in[0];
    const float* qw  = (const float*)d_in[1];
    const float* kw  = (const float*)d_in[2];
    const float* vw  = (const float*)d_in[3];
    const float* ow  = (const float*)d_in[4];
    const float* qnw = (const float*)d_in[5];
    const float* knw = (const float*)d_in[6];
    float* out = (float*)d_out;

    __half *gxh, *gqh, *gkh, *gvt, *goh, *wqkv, *wto;
    cudaGetSymbolAddress((void**)&gxh, g_xh);
    cudaGetSymbolAddress((void**)&gqh, g_qh);
    cudaGetSymbolAddress((void**)&gkh, g_kh);
    cudaGetSymbolAddress((void**)&gvt, g_vt);
    cudaGetSymbolAddress((void**)&goh, g_oh);
    cudaGetSymbolAddress((void**)&wqkv, g_wqkv);
    cudaGetSymbolAddress((void**)&wto, g_wto);

    const int M = MROWS;     // 4096
    const int NH = NQ * HD;  // 2048

    cudaFuncSetAttribute(gemm_h5<0>, cudaFuncAttributeMaxDynamicSharedMemorySize, 61440);
    cudaFuncSetAttribute(gemm_h5<1>, cudaFuncAttributeMaxDynamicSharedMemorySize, 67584);

    // 1: x -> half
    cvt_half<<<(M * Dd) / 2048, 256>>>(x, gxh);
    // 2: fused qkv weight transpose
    transpose_qkv<<<dim3(128, 64), 256>>>(qw, kw, vw, wqkv);
    // 3: rope table (must precede fused epilogue)
    rope_table<<<(Tt * 64 + 255) / 256, 256>>>();
    // 4: fused QKV projection + rms + rope + V-transpose (profiled)
    gemm_h5<1><<<dim3(32, 32), 256, 67584>>>(gxh, wqkv, nullptr, gqh, gkh, gvt,
                                             qnw, knw, M, 4096, Dd);
    // 5: o_w transpose
    transpose_h<<<dim3(Dd / 32, NH / 32), 256>>>(ow, wto, NH, Dd);
    // 6: flash attention
    size_t fsmem = (size_t)(2 * 8704 + 2 * 9216 + 8 * 1152) * sizeof(__half); // 90112
    cudaFuncSetAttribute(flash_h2, cudaFuncAttributeMaxDynamicSharedMemorySize, (int)fsmem);
    flash_h2<<<dim3(Tt / 128, NQ, Bb), 256, fsmem>>>(gqh, gkh, gvt, goh);
    // 7: output projection
    gemm_h5<0><<<dim3(Dd / 128, M / 128), 256, 61440>>>(goh, wto, out, nullptr, nullptr,
                                                        nullptr, nullptr, nullptr, M, Dd, NH);
}